// round 13
// baseline (speedup 1.0000x reference)
#include <cuda_runtime.h>
#include <cuda_fp16.h>
#include <math.h>
#include <stdint.h>

#define BB 4
#define NN 2048
#define DD 512
#define HH 8
#define EE 4
#define RR 4
#define TOK (BB*NN)      /* 8192 */
#define HID (RR*DD)      /* 2048 */

// weight fp16 cache offsets (halves)
#define W_QKV_OFF 0
#define W_O_OFF   786432
#define W1_OFF    1048576
#define W2_OFF    2097152
#define W_TOTAL   3145728

// ---------------- scratch ----------------
__device__ float g_probs[TOK*EE];
__device__ unsigned g_sorted[BB*EE*NN];
__device__ int    g_perm[TOK];
__device__ float  g_rps[TOK];
__device__ __align__(16) __half g_wh[W_TOTAL];
__device__ __align__(16) __half g_h[TOK*DD];
__device__ __align__(16) __half g_qkv[TOK*3*DD];
__device__ __align__(16) __half g_o[TOK*DD];
__device__ __align__(16) float  g_z[TOK*DD];
__device__ __align__(16) __half g_hid[(size_t)TOK*HID];

__device__ __forceinline__ int d_of_tile(int tb) {
    return tb < 8 ? 64 : tb < 12 ? 128 : tb < 14 ? 256 : 512;
}

// ---------------- helpers ----------------
__device__ __forceinline__ void mma_f16(float* d, const uint32_t* a, uint32_t b0, uint32_t b1) {
    asm volatile("mma.sync.aligned.m16n8k16.row.col.f32.f16.f16.f32 "
                 "{%0,%1,%2,%3}, {%4,%5,%6,%7}, {%8,%9}, {%0,%1,%2,%3};\n"
                 : "+f"(d[0]), "+f"(d[1]), "+f"(d[2]), "+f"(d[3])
                 : "r"(a[0]), "r"(a[1]), "r"(a[2]), "r"(a[3]), "r"(b0), "r"(b1));
}
__device__ __forceinline__ void ldsm_x4(uint32_t& r0, uint32_t& r1, uint32_t& r2, uint32_t& r3, uint32_t addr) {
    asm volatile("ldmatrix.sync.aligned.m8n8.x4.shared.b16 {%0,%1,%2,%3}, [%4];"
                 : "=r"(r0), "=r"(r1), "=r"(r2), "=r"(r3) : "r"(addr));
}
__device__ __forceinline__ void ldsm_x2t(uint32_t& r0, uint32_t& r1, uint32_t addr) {
    asm volatile("ldmatrix.sync.aligned.m8n8.x2.trans.shared.b16 {%0,%1}, [%2];"
                 : "=r"(r0), "=r"(r1) : "r"(addr));
}
__device__ __forceinline__ uint32_t packh2(float a, float b) {
    __half2 h = __floats2half2_rn(a, b);
    return *(uint32_t*)&h;
}
__device__ __forceinline__ void cp_async16(uint32_t saddr, const void* gaddr) {
    asm volatile("cp.async.ca.shared.global [%0], [%1], 16;\n" :: "r"(saddr), "l"(gaddr));
}
__device__ __forceinline__ void cp_commit() {
    asm volatile("cp.async.commit_group;\n" ::: "memory");
}
__device__ __forceinline__ void cp_wait0() {
    asm volatile("cp.async.wait_group 0;\n" ::: "memory");
}
__device__ __forceinline__ void cp_wait1() {
    asm volatile("cp.async.wait_group 1;\n" ::: "memory");
}

// ---------------- prep: LN1 + router (blocks 0..1023) fused with wconv (blocks 1024..4095) ----------------
__global__ void prep_kernel(const float* __restrict__ x,
                            const float* __restrict__ g,
                            const float* __restrict__ b,
                            __half* __restrict__ o,
                            const float* __restrict__ rw,
                            const float* __restrict__ rb,
                            const float* __restrict__ wqkv, const float* __restrict__ wo,
                            const float* __restrict__ w1,   const float* __restrict__ w2)
{
    if (blockIdx.x >= TOK/8) {
        size_t off = ((size_t)(blockIdx.x - TOK/8)*256 + threadIdx.x) * 4;
        if (off >= W_TOTAL) return;
        const float* src;
        if (off < W_O_OFF)      src = wqkv + off;
        else if (off < W1_OFF)  src = wo + (off - W_O_OFF);
        else if (off < W2_OFF)  src = w1 + (off - W1_OFF);
        else                    src = w2 + (off - W2_OFF);
        float4 v = *(const float4*)src;
        *(uint2*)(g_wh + off) = make_uint2(packh2(v.x, v.y), packh2(v.z, v.w));
        return;
    }
    int lane = threadIdx.x & 31, warp = threadIdx.x >> 5;
    int row = blockIdx.x * 8 + warp;
    const float* xr = x + (size_t)row * DD;
    float4 v[4];
    float s = 0.f, q = 0.f;
    float lg0=0.f, lg1=0.f, lg2=0.f, lg3=0.f;
    #pragma unroll
    for (int i = 0; i < 4; i++) {
        int c0 = (i*32 + lane)*4;
        v[i] = *(const float4*)(xr + c0);
        s += v[i].x + v[i].y + v[i].z + v[i].w;
        q += v[i].x*v[i].x + v[i].y*v[i].y + v[i].z*v[i].z + v[i].w*v[i].w;
        #pragma unroll
        for (int j = 0; j < 4; j++) {
            float xv = (&v[i].x)[j];
            float4 r4 = *(const float4*)(rw + (c0 + j)*4);
            lg0 += xv*r4.x; lg1 += xv*r4.y; lg2 += xv*r4.z; lg3 += xv*r4.w;
        }
    }
    #pragma unroll
    for (int off = 16; off > 0; off >>= 1) {
        s += __shfl_xor_sync(0xffffffffu, s, off);
        q += __shfl_xor_sync(0xffffffffu, q, off);
        lg0 += __shfl_xor_sync(0xffffffffu, lg0, off);
        lg1 += __shfl_xor_sync(0xffffffffu, lg1, off);
        lg2 += __shfl_xor_sync(0xffffffffu, lg2, off);
        lg3 += __shfl_xor_sync(0xffffffffu, lg3, off);
    }
    if (lane == 0) {
        float l[4] = {lg0 + rb[0], lg1 + rb[1], lg2 + rb[2], lg3 + rb[3]};
        float mx = fmaxf(fmaxf(l[0], l[1]), fmaxf(l[2], l[3]));
        float p[4]; float Z = 0.f;
        #pragma unroll
        for (int e = 0; e < 4; e++) { p[e] = expf(l[e] - mx); Z += p[e]; }
        float inv = 1.f/Z;
        *(float4*)(g_probs + row*4) = make_float4(p[0]*inv, p[1]*inv, p[2]*inv, p[3]*inv);
    }
    float mu = s * (1.f/DD);
    float var = q * (1.f/DD) - mu*mu;
    float rstd = rsqrtf(var + 1e-5f);
    __half* orow = o + (size_t)row * DD;
    #pragma unroll
    for (int i = 0; i < 4; i++) {
        int idx = (i*32 + lane)*4;
        float4 gv = *(const float4*)(g + idx);
        float4 bv = *(const float4*)(b + idx);
        float o0 = (v[i].x - mu)*rstd*gv.x + bv.x;
        float o1 = (v[i].y - mu)*rstd*gv.y + bv.y;
        float o2 = (v[i].z - mu)*rstd*gv.z + bv.z;
        float o3 = (v[i].w - mu)*rstd*gv.w + bv.w;
        *(uint2*)(orow + idx) = make_uint2(packh2(o0, o1), packh2(o2, o3));
    }
}

// ---------------- plain layernorm (sorted order, LN2), warp per row ----------------
__global__ void ln_kernel(const float* __restrict__ x,
                          const float* __restrict__ g,
                          const float* __restrict__ b,
                          __half* __restrict__ o)
{
    int lane = threadIdx.x & 31, warp = threadIdx.x >> 5;
    int row = blockIdx.x * 8 + warp;
    const float* xr = x + (size_t)row * DD;
    float4 v[4];
    float s = 0.f, q = 0.f;
    #pragma unroll
    for (int i = 0; i < 4; i++) {
        v[i] = *(const float4*)(xr + (i*32 + lane)*4);
        s += v[i].x + v[i].y + v[i].z + v[i].w;
        q += v[i].x*v[i].x + v[i].y*v[i].y + v[i].z*v[i].z + v[i].w*v[i].w;
    }
    #pragma unroll
    for (int off = 16; off > 0; off >>= 1) {
        s += __shfl_xor_sync(0xffffffffu, s, off);
        q += __shfl_xor_sync(0xffffffffu, q, off);
    }
    float mu = s * (1.f/DD);
    float var = q * (1.f/DD) - mu*mu;
    float rstd = rsqrtf(var + 1e-5f);
    __half* orow = o + (size_t)row * DD;
    #pragma unroll
    for (int i = 0; i < 4; i++) {
        int idx = (i*32 + lane)*4;
        float4 gv = *(const float4*)(g + idx);
        float4 bv = *(const float4*)(b + idx);
        float o0 = (v[i].x - mu)*rstd*gv.x + bv.x;
        float o1 = (v[i].y - mu)*rstd*gv.y + bv.y;
        float o2 = (v[i].z - mu)*rstd*gv.z + bv.z;
        float o3 = (v[i].w - mu)*rstd*gv.w + bv.w;
        *(uint2*)(orow + idx) = make_uint2(packh2(o0, o1), packh2(o2, o3));
    }
}

// ---------------- parallel per-(b,e) sort, shuffle-bitonic ----------------
__global__ void sort_kernel()
{
    __shared__ unsigned long long keys[NN];
    int b = blockIdx.x >> 2, e = blockIdx.x & 3;
    int t = threadIdx.x;                      // 1024
    {
        unsigned pb0 = __float_as_uint(g_probs[(b*NN + 2*t)*4 + e]);
        unsigned pb1 = __float_as_uint(g_probs[(b*NN + 2*t + 1)*4 + e]);
        keys[2*t]   = ((unsigned long long)(~pb0) << 32) | (unsigned)(2*t);
        keys[2*t+1] = ((unsigned long long)(~pb1) << 32) | (unsigned)(2*t + 1);
    }
    __syncthreads();
    for (int k = 2; k <= NN; k <<= 1) {
        for (int j = k >> 1; j >= 64; j >>= 1) {
            #pragma unroll
            for (int w = 0; w < 2; w++) {
                int idx = t + w*1024;
                int l = idx ^ j;
                if (l > idx) {
                    bool asc = ((idx & k) == 0);
                    unsigned long long a = keys[idx], c2 = keys[l];
                    if ((a > c2) == asc) { keys[idx] = c2; keys[l] = a; }
                }
            }
            __syncthreads();
        }
        unsigned long long k0 = keys[2*t], k1 = keys[2*t+1];
        bool asc = ((2*t) & k) == 0;
        int jstart = (k >> 1) < 32 ? (k >> 1) : 32;
        for (int j = jstart; j >= 2; j >>= 1) {
            int hf = j >> 1;
            bool iless = ((t & hf) == 0);
            unsigned long long o0 = __shfl_xor_sync(0xffffffffu, k0, hf);
            unsigned long long o1 = __shfl_xor_sync(0xffffffffu, k1, hf);
            bool keepmin = (iless == asc);
            k0 = keepmin ? (k0 < o0 ? k0 : o0) : (k0 > o0 ? k0 : o0);
            k1 = keepmin ? (k1 < o1 ? k1 : o1) : (k1 > o1 ? k1 : o1);
        }
        {
            unsigned long long lo = k0 < k1 ? k0 : k1;
            unsigned long long hi = k0 < k1 ? k1 : k0;
            k0 = asc ? lo : hi;
            k1 = asc ? hi : lo;
        }
        keys[2*t] = k0; keys[2*t+1] = k1;
        __syncthreads();
    }
    g_sorted[(b*4+e)*NN + 2*t]   = (unsigned)(keys[2*t] & 0xFFFFFFFFull);
    g_sorted[(b*4+e)*NN + 2*t+1] = (unsigned)(keys[2*t+1] & 0xFFFFFFFFull);
}

// ---------------- claim: 512 threads, 4 tokens/thread, packed perm scan ----------------
__global__ void claim_kernel(float* __restrict__ out, int out_size)
{
    __shared__ int asg[NN];
    __shared__ int wsum[16];
    __shared__ unsigned long long wsum64[16];
    const int caps[4]  = {1024, 512, 256, 256};
    const int base4[4] = {0, 1024, 1536, 1792};
    int b = blockIdx.x, t = threadIdx.x;      // 512 threads
    int lane = t & 31, wid = t >> 5;          // 16 warps
    #pragma unroll
    for (int w = 0; w < 4; w++) asg[4*t + w] = -1;
    __syncthreads();

    for (int e = 3; e >= 0; e--) {
        int ids[4], f[4];
        int s = 0;
        #pragma unroll
        for (int w = 0; w < 4; w++) {
            ids[w] = (int)g_sorted[(b*4+e)*NN + 4*t + w];
            f[w] = (asg[ids[w]] < 0) ? 1 : 0;
            s += f[w];
        }
        int sc = s;
        #pragma unroll
        for (int o = 1; o < 32; o <<= 1) {
            int u = __shfl_up_sync(0xffffffff, sc, o);
            if (lane >= o) sc += u;
        }
        if (lane == 31) wsum[wid] = sc;
        __syncthreads();
        if (wid == 0 && lane < 16) {
            int w = wsum[lane];
            #pragma unroll
            for (int o = 1; o < 16; o <<= 1) {
                int u = __shfl_up_sync(0x0000ffffu, w, o);
                if (lane >= o) w += u;
            }
            wsum[lane] = w;
        }
        __syncthreads();
        int base = (wid > 0 ? wsum[wid-1] : 0) + (sc - s);
        int cap = caps[e];
        int run = 0;
        #pragma unroll
        for (int w = 0; w < 4; w++) {
            run += f[w];
            if (f[w] && (base + run) <= cap) asg[ids[w]] = e;
        }
        __syncthreads();
    }

    int a[4];
    unsigned long long pk = 0;
    #pragma unroll
    for (int w = 0; w < 4; w++) {
        a[w] = asg[4*t + w];
        pk += 1ull << (16 * a[w]);
    }
    unsigned long long sc64 = pk;
    #pragma unroll
    for (int o = 1; o < 32; o <<= 1) {
        unsigned long long u = __shfl_up_sync(0xffffffff, sc64, o);
        if (lane >= o) sc64 += u;
    }
    if (lane == 31) wsum64[wid] = sc64;
    __syncthreads();
    if (wid == 0 && lane < 16) {
        unsigned long long w = wsum64[lane];
        #pragma unroll
        for (int o = 1; o < 16; o <<= 1) {
            unsigned long long u = __shfl_up_sync(0x0000ffffu, w, o);
            if (lane >= o) w += u;
        }
        wsum64[lane] = w;
    }
    __syncthreads();
    unsigned long long base64 = (wid > 0 ? wsum64[wid-1] : 0ull) + (sc64 - pk);
    int cnt[4];
    #pragma unroll
    for (int e = 0; e < 4; e++) cnt[e] = (int)((base64 >> (16*e)) & 0xFFFF);
    #pragma unroll
    for (int w = 0; w < 4; w++) {
        int e = a[w];
        int gi = b*NN + 4*t + w;
        int pos = b*NN + base4[e] + cnt[e];
        cnt[e]++;
        g_perm[pos] = gi;
        g_rps[pos] = g_probs[gi*4 + e];
        if (out_size >= TOK*DD + TOK)   out[TOK*DD + gi] = (float)e;
        if (out_size >= TOK*DD + 2*TOK) out[TOK*DD + TOK + gi] = g_probs[gi*4 + e];
    }
}

// ---------------- fp16 GEMM, cp.async 3-stage, 128x128 tile, K-chunk 64, fused epilogues ----------------
__device__ __forceinline__ float gelu_t(float v) {
    float c = v*v*v;
    float t = tanhf(0.7978845608028654f*(v + 0.044715f*c));
    return 0.5f*v*(1.f+t);
}

#define ASTAGE 18432   /* 128*72*2 bytes */
#define BSTAGE 17408   /* 64*136*2 bytes */
#define GEMM_SMEM (3*(ASTAGE + BSTAGE))   /* 107520 */

// EPI 0: qkv (A row-gather via perm; output mask; skip empty col tiles)   Keff=d
// EPI 1: o-proj  z = x[perm] + mask*(c+b_o)                                Keff=d
// EPI 2: ff1 gelu (skip col tiles past 4d)                                 Keff=d
// EPI 3: ff2  out[perm] = z + gate*mask*(c+b2f)                            Keff=4d
template<int EPI>
__global__ void __launch_bounds__(256) tgemm_kernel(
                             const __half* __restrict__ A, const __half* __restrict__ B,
                             void* __restrict__ Cv, int N, int K,
                             const float* __restrict__ bias,
                             const float* __restrict__ add,
                             const float* __restrict__ alpha)
{
    int bx = blockIdx.x, by = blockIdx.y;
    int d = d_of_tile(by & 15);
    int col0 = bx * 128;
    int tid  = threadIdx.x;         // 256
    int lane = tid & 31;
    int warp = tid >> 5;

    if (EPI == 0) { if ((col0 & 511) >= d) return; }
    if (EPI == 2) { if (col0 >= 4*d) return; }
    if (EPI == 1 || EPI == 3) {
        if (col0 >= d) {
            int rr = tid >> 1;
            int cc = (tid & 1) * 64;
            int rg = by*128 + rr;
            int orig = g_perm[rg];
            const float* src = (EPI == 1) ? (add + (size_t)orig*N) : (add + (size_t)rg*N);
            float* dst = (EPI == 1) ? ((float*)Cv + (size_t)rg*N) : ((float*)Cv + (size_t)orig*N);
            #pragma unroll
            for (int j = 0; j < 64; j += 4)
                *(float4*)(dst + col0 + cc + j) = *(const float4*)(src + col0 + cc + j);
            return;
        }
    }
    int Keff = (EPI == 3) ? 4*d : d;
    int nIters = Keff >> 6;

    extern __shared__ __align__(16) char dynsm[];
    uint32_t asb = (uint32_t)__cvta_generic_to_shared(dynsm);
    uint32_t bsb = asb + 3*ASTAGE;

    int wm = warp >> 2, wn = warp & 3;
    float c[4][4][4];
    #pragma unroll
    for (int i=0;i<4;i++)
        #pragma unroll
        for (int j=0;j<4;j++)
            #pragma unroll
            for (int r=0;r<4;r++) c[i][j][r]=0.f;

    int ar  = tid >> 1;             // 0..127
    int ach = (tid & 1) * 32;       // half offset 0/32
    int rowA0 = by*128 + ar;
    int rowA = (EPI == 0) ? g_perm[rowA0] : rowA0;
    const __half* Ag = A + (size_t)rowA*K + ach;
    uint32_t aSlot = asb + ar*144 + ach*2;
    int bk  = tid >> 2;             // 0..63
    int bn0 = (tid & 3) * 32;       // half offset 0..96
    const __half* Bg = B + (size_t)bk*N + col0 + bn0;
    uint32_t bSlot = bsb + bk*272 + bn0*2;

    // prologue: stages 0 and 1 (K-chunk = 64)
    #pragma unroll
    for (int p = 0; p < 4; p++) {
        cp_async16(aSlot + p*16, Ag + p*8);
        cp_async16(bSlot + p*16, Bg + p*8);
    }
    cp_commit();
    int inflight = 1;
    if (nIters > 1) {
        const __half* Ag1 = Ag + 64;
        const __half* Bg1 = Bg + (size_t)64*N;
        #pragma unroll
        for (int p = 0; p < 4; p++) {
            cp_async16(aSlot + ASTAGE + p*16, Ag1 + p*8);
            cp_async16(bSlot + BSTAGE + p*16, Bg1 + p*8);
        }
        cp_commit();
        inflight = 2;
    }

    int st = 0;
    for (int it = 0; it < nIters; it++) {
        if (inflight == 2) cp_wait1(); else cp_wait0();
        inflight--;
        __syncthreads();
        if (it + 2 < nIters) {
            int sn = st + 2; if (sn >= 3) sn -= 3;
            const __half* Agn = Ag + (it + 2)*64;
            const __half* Bgn = Bg + (size_t)((it + 2)*64)*N;
            #pragma unroll
            for (int p = 0; p < 4; p++) {
                cp_async16(aSlot + sn*ASTAGE + p*16, Agn + p*8);
                cp_async16(bSlot + sn*BSTAGE + p*16, Bgn + p*8);
            }
            cp_commit();
            inflight++;
        }
        uint32_t ab = asb + st*ASTAGE;
        uint32_t bb = bsb + st*BSTAGE;
        #pragma unroll
        for (int kk = 0; kk < 64; kk += 16) {
            uint32_t af[4][4];
            #pragma unroll
            for (int am = 0; am < 4; am++) {
                int m = lane >> 3;
                int row = wm*64 + am*16 + (lane & 7) + (m & 1)*8;
                int col = kk + (m >> 1)*8;
                ldsm_x4(af[am][0], af[am][1], af[am][2], af[am][3], ab + row*144 + col*2);
            }
            #pragma unroll
            for (int an = 0; an < 4; an++) {
                int brow = kk + (lane & 15);
                int bcol = wn*32 + an*8;
                uint32_t b0, b1;
                ldsm_x2t(b0, b1, bb + brow*272 + bcol*2);
                #pragma unroll
                for (int am = 0; am < 4; am++)
                    mma_f16(c[am][an], af[am], b0, b1);
            }
        }
        st++; if (st >= 3) st -= 3;
    }

    float aval = (EPI == 3) ? alpha[0] : 0.f;
    #pragma unroll
    for (int am = 0; am < 4; am++) {
        int r0 = by*128 + wm*64 + am*16 + (lane>>2);
        int r1 = r0 + 8;
        float gate0 = (EPI == 3) ? (aval * g_rps[r0] + 1.f) : 0.f;
        float gate1 = (EPI == 3) ? (aval * g_rps[r1] + 1.f) : 0.f;
        int org0 = (EPI == 1 || EPI == 3) ? g_perm[r0] : 0;
        int org1 = (EPI == 1 || EPI == 3) ? g_perm[r1] : 0;
        #pragma unroll
        for (int an = 0; an < 4; an++) {
            int col = col0 + wn*32 + an*8 + (lane&3)*2;
            #pragma unroll
            for (int h2 = 0; h2 < 2; h2++) {
                int r = h2 ? r1 : r0;
                int org = h2 ? org1 : org0;
                float gate = h2 ? gate1 : gate0;
                float v0 = c[am][an][2*h2], v1 = c[am][an][2*h2+1];
                if (EPI == 0) {
                    float o0 = ((col & 511) < d)     ? v0 : 0.f;
                    float o1 = (((col+1) & 511) < d) ? v1 : 0.f;
                    *(uint32_t*)((__half*)Cv + (size_t)r*N + col) = packh2(o0, o1);
                } else if (EPI == 1) {
                    size_t xi = (size_t)org*N + col;
                    float o0 = add[xi]   + ((col   < d) ? (v0 + bias[col])   : 0.f);
                    float o1 = add[xi+1] + ((col+1 < d) ? (v1 + bias[col+1]) : 0.f);
                    *(float2*)((float*)Cv + (size_t)r*N + col) = make_float2(o0, o1);
                } else if (EPI == 2) {
                    float o0 = gelu_t(v0 + bias[col]);
                    float o1 = gelu_t(v1 + bias[col+1]);
                    *(uint32_t*)((__half*)Cv + (size_t)r*N + col) = packh2(o0, o1);
                } else {
                    size_t zi = (size_t)r*N + col;
                    float z0 = (col   < d) ? (v0 + bias[col])   : 0.f;
                    float z1 = (col+1 < d) ? (v1 + bias[col+1]) : 0.f;
                    float o0 = add[zi]   + gate * z0;
                    float o1 = add[zi+1] + gate * z1;
                    *(float2*)((float*)Cv + (size_t)org*N + col) = make_float2(o0, o1);
                }
            }
        }
    }
}

// ---------------- fp16 flash attention, intra-block split-K (2 groups) ----------------
#define QS_OFF 0
#define KS_OFF(g) (4608 + (g)*4608)
#define VS_OFF(g) (13824 + (g)*4608)

__global__ void attn_kernel()   // 256 threads = 2 warp-groups of 4 warps
{
    __shared__ __align__(16) __half sm[23040];

    int b = blockIdx.y;
    int qi = blockIdx.x;            // 0..79
    int h, qt;
    if (qi < 32)      { h = 0; qt = qi; }
    else if (qi < 48) { h = 1; qt = 16 + (qi - 32); }
    else if (qi < 56) { h = 2; qt = 24 + (qi - 48); }
    else if (qi < 64) { h = 3; qt = 24 + (qi - 56); }
    else              { h = 4 + ((qi - 64) >> 2); qt = 28 + ((qi - 64) & 3); }
    int kt0 = (h == 0) ? 0 : (h == 1) ? 16 : (h < 4) ? 24 : 28;
    int nz = kt0 * 64;

    int tid = threadIdx.x;
    int lane = tid & 31;
    int warp = tid >> 5;
    int grp = warp >> 2;            // 0/1
    int w4 = warp & 3;
    int ltid = tid & 127;

    int half = (32 - kt0) >> 1;
    int ktbeg = kt0 + grp*half;

    __half* Qs = sm + QS_OFF;
    __half* Ks = sm + KS_OFF(grp);
    __half* Vs = sm + VS_OFF(grp);
    uint32_t vsb = (uint32_t)__cvta_generic_to_shared(Vs);

    const __half* qb = g_qkv + (size_t)(b*NN + qt*64)*1536 + h*64;
    for (int i = tid; i < 512; i += 256) {
        int n = i >> 3, c8 = (i & 7) * 8;
        *(uint4*)(&Qs[n*72 + c8]) = *(const uint4*)(qb + (size_t)n*1536 + c8);
    }
    __syncthreads();

    uint32_t qf[4][4];
    {
        int r = w4*16 + (lane >> 2);
        #pragma unroll
        for (int ka = 0; ka < 4; ka++) {
            int cc = ka*16 + (lane & 3)*2;
            qf[ka][0] = *(const uint32_t*)(&Qs[r*72 + cc]);
            qf[ka][1] = *(const uint32_t*)(&Qs[(r+8)*72 + cc]);
            qf[ka][2] = *(const uint32_t*)(&Qs[r*72 + cc + 8]);
            qf[ka][3] = *(const uint32_t*)(&Qs[(r+8)*72 + cc + 8]);
        }
    }

    float o[8][4];
    #pragma unroll
    for (int i=0;i<8;i++)
        #pragma unroll
        for (int j=0;j<4;j++) o[i][j]=0.f;
    float m0, m1, l0, l1;
    if (grp == 0 && nz > 0) { m0 = 0.f; m1 = 0.f; l0 = (float)nz; l1 = (float)nz; }
    else                    { m0 = -1e30f; m1 = -1e30f; l0 = 0.f; l1 = 0.f; }

    for (int ii = 0; ii < half; ii++) {
        int kt = ktbeg + ii;
        __syncthreads();
        const __half* kb = g_qkv + (size_t)(b*NN + kt*64)*1536 + 512 + h*64;
        for (int i = ltid; i < 512; i += 128) {
            int n = i >> 3, c8 = (i & 7) * 8;
            *(uint4*)(&Ks[n*72 + c8]) = *(const uint4*)(kb + (size_t)n*1536 + c8);
            *(uint4*)(&Vs[n*72 + c8]) = *(const uint4*)(kb + 512 + (size_t)n*1536 + c8);
        }
        __syncthreads();

        float s[8][4];
        #pragma unroll
        for (int i=0;i<8;i++)
            #pragma unroll
            for (int j=0;j<4;j++) s[i][j]=0.f;
        #pragma unroll
        for (int ka = 0; ka < 4; ka++) {
            #pragma unroll
            for (int na = 0; na < 8; na++) {
                int n = na*8 + (lane >> 2);
                int k = ka*16 + (lane & 3)*2;
                uint32_t b0 = *(const uint32_t*)(&Ks[n*72 + k]);
                uint32_t b1 = *(const uint32_t*)(&Ks[n*72 + k + 8]);
                mma_f16(s[na], qf[ka], b0, b1);
            }
        }

        float mx0 = -1e30f, mx1 = -1e30f;
        #pragma unroll
        for (int na = 0; na < 8; na++) {
            s[na][0]*=0.125f; s[na][1]*=0.125f; s[na][2]*=0.125f; s[na][3]*=0.125f;
            mx0 = fmaxf(mx0, fmaxf(s[na][0], s[na][1]));
            mx1 = fmaxf(mx1, fmaxf(s[na][2], s[na][3]));
        }
        mx0 = fmaxf(mx0, __shfl_xor_sync(0xffffffffu, mx0, 1));
        mx0 = fmaxf(mx0, __shfl_xor_sync(0xffffffffu, mx0, 2));
        mx1 = fmaxf(mx1, __shfl_xor_sync(0xffffffffu, mx1, 1));
        mx1 = fmaxf(mx1, __shfl_xor_sync(0xffffffffu, mx1, 2));
        float mn0 = fmaxf(m0, mx0), mn1 = fmaxf(m1, mx1);
        float sc0 = __expf(m0 - mn0), sc1 = __expf(m1 - mn1);
        m0 = mn0; m1 = mn1;

        float sum0 = 0.f, sum1 = 0.f;
        #pragma unroll
        for (int na = 0; na < 8; na++) {
            s[na][0] = __expf(s[na][0] - m0);
            s[na][1] = __expf(s[na][1] - m0);
            s[na][2] = __expf(s[na][2] - m1);
            s[na][3] = __expf(s[na][3] - m1);
            sum0 += s[na][0] + s[na][1];
            sum1 += s[na][2] + s[na][3];
        }
        sum0 += __shfl_xor_sync(0xffffffffu, sum0, 1);
        sum0 += __shfl_xor_sync(0xffffffffu, sum0, 2);
        sum1 += __shfl_xor_sync(0xffffffffu, sum1, 1);
        sum1 += __shfl_xor_sync(0xffffffffu, sum1, 2);
        l0 = l0*sc0 + sum0;
        l1 = l1*sc1 + sum1;

        #pragma unroll
        for (int da = 0; da < 8; da++) {
            o[da][0]*=sc0; o[da][1]*=sc0; o[da][2]*=sc1; o[da][3]*=sc1;
        }

        #pragma unroll
        for (int ka = 0; ka < 4; ka++) {
            uint32_t pa[4];
            pa[0] = packh2(s[2*ka][0],   s[2*ka][1]);
            pa[1] = packh2(s[2*ka][2],   s[2*ka][3]);
            pa[2] = packh2(s[2*ka+1][0], s[2*ka+1][1]);
            pa[3] = packh2(s[2*ka+1][2], s[2*ka+1][3]);
            uint32_t rowaddr = vsb + (ka*16 + (lane & 15))*144;
            #pragma unroll
            for (int da = 0; da < 8; da++) {
                uint32_t b0, b1;
                ldsm_x2t(b0, b1, rowaddr + da*16);
                mma_f16(o[da], pa, b0, b1);
            }
        }
    }

    __syncthreads();
    float* so = (float*)sm;
    float* sml = so + 64*66;
    int r0 = w4*16 + (lane >> 2);
    int r1 = r0 + 8;
    if (grp == 1) {
        #pragma unroll
        for (int da = 0; da < 8; da++) {
            int col = da*8 + (lane&3)*2;
            *(float2*)(&so[r0*66 + col]) = make_float2(o[da][0], o[da][1]);
            *(float2*)(&so[r1*66 + col]) = make_float2(o[da][2], o[da][3]);
        }
        if ((lane & 3) == 0) {
            sml[r0] = m0; sml[64 + r0] = l0;
            sml[r1] = m1; sml[64 + r1] = l1;
        }
    }
    __syncthreads();
    if (grp == 0) {
        float m1s0 = sml[r0], l1s0 = sml[64 + r0];
        float m1s1 = sml[r1], l1s1 = sml[64 + r1];
        float M0 = fmaxf(m0, m1s0), M1 = fmaxf(m1, m1s1);
        float a0 = __expf(m0 - M0), b0s = __expf(m1s0 - M0);
        float a1 = __expf(m1 - M1), b1s = __expf(m1s1 - M1);
        float L0 = l0*a0 + l1s0*b0s;
        float L1 = l1*a1 + l1s1*b1s;
        float inv0 = 1.f / L0, inv1 = 1.f / L1;
        int tok0 = b*NN + qt*64 + r0;
        int tok1 = tok0 + 8;
        #pragma unroll
        for (int da = 0; da < 8; da++) {
            int col = da*8 + (lane&3)*2;
            float2 p0 = *(float2*)(&so[r0*66 + col]);
            float2 p1 = *(float2*)(&so[r1*66 + col]);
            float f00 = (o[da][0]*a0 + p0.x*b0s) * inv0;
            float f01 = (o[da][1]*a0 + p0.y*b0s) * inv0;
            float f10 = (o[da][2]*a1 + p1.x*b1s) * inv1;
            float f11 = (o[da][3]*a1 + p1.y*b1s) * inv1;
            int gcol = h*64 + col;
            *(uint32_t*)(g_o + (size_t)tok0*DD + gcol) = packh2(f00, f01);
            *(uint32_t*)(g_o + (size_t)tok1*DD + gcol) = packh2(f10, f11);
        }
    }
}

// ---------------- launcher ----------------
extern "C" void kernel_launch(void* const* d_in, const int* in_sizes, int n_in,
                              void* d_out, int out_size)
{
    const float* x     = (const float*)d_in[0];
    const float* r_w   = (const float*)d_in[1];
    const float* r_b   = (const float*)d_in[2];
    const float* g1    = (const float*)d_in[3];
    const float* b1    = (const float*)d_in[4];
    const float* g2    = (const float*)d_in[5];
    const float* b2    = (const float*)d_in[6];
    const float* w_qkv = (const float*)d_in[7];
    const float* w_o   = (const float*)d_in[8];
    const float* b_o   = (const float*)d_in[9];
    const float* w1    = (const float*)d_in[10];
    const float* b1f   = (const float*)d_in[11];
    const float* w2    = (const float*)d_in[12];
    const float* b2f   = (const float*)d_in[13];
    const float* alpha = (const float*)d_in[14];
    float* out = (float*)d_out;

    __half *p_h, *p_qkv, *p_o, *p_hid, *p_wh;
    float *p_z;
    cudaGetSymbolAddress((void**)&p_h,   g_h);
    cudaGetSymbolAddress((void**)&p_qkv, g_qkv);
    cudaGetSymbolAddress((void**)&p_o,   g_o);
    cudaGetSymbolAddress((void**)&p_z,   g_z);
    cudaGetSymbolAddress((void**)&p_hid, g_hid);
    cudaGetSymbolAddress((void**)&p_wh,  g_wh);

    cudaFuncSetAttribute(tgemm_kernel<0>, cudaFuncAttributeMaxDynamicSharedMemorySize, GEMM_SMEM);
    cudaFuncSetAttribute(tgemm_kernel<1>, cudaFuncAttributeMaxDynamicSharedMemorySize, GEMM_SMEM);
    cudaFuncSetAttribute(tgemm_kernel<2>, cudaFuncAttributeMaxDynamicSharedMemorySize, GEMM_SMEM);
    cudaFuncSetAttribute(tgemm_kernel<3>, cudaFuncAttributeMaxDynamicSharedMemorySize, GEMM_SMEM);

    // LN1 + router + weight conversion (fused)
    prep_kernel<<<TOK/8 + (W_TOTAL/4 + 255)/256, 256>>>(x, g1, b1, p_h, r_w, r_b,
                                                        w_qkv, w_o, w1, w2);
    sort_kernel<<<BB*EE, 1024>>>();
    claim_kernel<<<BB, 512>>>(out, out_size);

    // attention path
    tgemm_kernel<0><<<dim3(1536/128, TOK/128), 256, GEMM_SMEM>>>(p_h, p_wh + W_QKV_OFF, p_qkv, 1536, 512,
                                                                 nullptr, nullptr, nullptr);
    attn_kernel<<<dim3(80, BB), 256>>>();
    tgemm_kernel<1><<<dim3(512/128, TOK/128), 256, GEMM_SMEM>>>(p_o, p_wh + W_O_OFF, p_z, 512, 512,
                                                                b_o, x, nullptr);

    // feed-forward path
    ln_kernel<<<TOK/8, 256>>>(p_z, g2, b2, p_h);
    tgemm_kernel<2><<<dim3(2048/128, TOK/128), 256, GEMM_SMEM>>>(p_h, p_wh + W1_OFF, p_hid, 2048, 512,
                                                                 b1f, nullptr, nullptr);
    tgemm_kernel<3><<<dim3(512/128, TOK/128), 256, GEMM_SMEM>>>(p_hid, p_wh + W2_OFF, out, 512, 2048,
                                                                b2f, p_z, alpha);
}

// round 14
// speedup vs baseline: 1.1116x; 1.1116x over previous
#include <cuda_runtime.h>
#include <cuda_fp16.h>
#include <math.h>
#include <stdint.h>

#define BB 4
#define NN 2048
#define DD 512
#define HH 8
#define EE 4
#define RR 4
#define TOK (BB*NN)      /* 8192 */
#define HID (RR*DD)      /* 2048 */

// weight fp16 cache offsets (halves)
#define W_QKV_OFF 0
#define W_O_OFF   786432
#define W1_OFF    1048576
#define W2_OFF    2097152
#define W_TOTAL   3145728

// ---------------- scratch ----------------
__device__ float g_probs[TOK*EE];
__device__ unsigned g_sorted[BB*EE*NN];
__device__ int    g_perm[TOK];
__device__ float  g_rps[TOK];
__device__ __align__(16) __half g_wh[W_TOTAL];
__device__ __align__(16) __half g_h[TOK*DD];
__device__ __align__(16) __half g_qkv[TOK*3*DD];
__device__ __align__(16) __half g_o[TOK*DD];
__device__ __align__(16) float  g_z[TOK*DD];
__device__ __align__(16) __half g_hid[(size_t)TOK*HID];

__device__ __forceinline__ int d_of_tile(int tb) {
    return tb < 8 ? 64 : tb < 12 ? 128 : tb < 14 ? 256 : 512;
}

// ---------------- helpers ----------------
__device__ __forceinline__ void mma_f16(float* d, const uint32_t* a, uint32_t b0, uint32_t b1) {
    asm volatile("mma.sync.aligned.m16n8k16.row.col.f32.f16.f16.f32 "
                 "{%0,%1,%2,%3}, {%4,%5,%6,%7}, {%8,%9}, {%0,%1,%2,%3};\n"
                 : "+f"(d[0]), "+f"(d[1]), "+f"(d[2]), "+f"(d[3])
                 : "r"(a[0]), "r"(a[1]), "r"(a[2]), "r"(a[3]), "r"(b0), "r"(b1));
}
__device__ __forceinline__ void ldsm_x4(uint32_t& r0, uint32_t& r1, uint32_t& r2, uint32_t& r3, uint32_t addr) {
    asm volatile("ldmatrix.sync.aligned.m8n8.x4.shared.b16 {%0,%1,%2,%3}, [%4];"
                 : "=r"(r0), "=r"(r1), "=r"(r2), "=r"(r3) : "r"(addr));
}
__device__ __forceinline__ void ldsm_x2t(uint32_t& r0, uint32_t& r1, uint32_t addr) {
    asm volatile("ldmatrix.sync.aligned.m8n8.x2.trans.shared.b16 {%0,%1}, [%2];"
                 : "=r"(r0), "=r"(r1) : "r"(addr));
}
__device__ __forceinline__ uint32_t packh2(float a, float b) {
    __half2 h = __floats2half2_rn(a, b);
    return *(uint32_t*)&h;
}
__device__ __forceinline__ void cp_async16(uint32_t saddr, const void* gaddr) {
    asm volatile("cp.async.ca.shared.global [%0], [%1], 16;\n" :: "r"(saddr), "l"(gaddr));
}
__device__ __forceinline__ void cp_commit() {
    asm volatile("cp.async.commit_group;\n" ::: "memory");
}
__device__ __forceinline__ void cp_waitg(int n) {
    if (n <= 0)      asm volatile("cp.async.wait_group 0;\n" ::: "memory");
    else if (n == 1) asm volatile("cp.async.wait_group 1;\n" ::: "memory");
    else             asm volatile("cp.async.wait_group 2;\n" ::: "memory");
}

// ---------------- prep: LN1 + router (blocks 0..1023) fused with wconv (blocks 1024..4095) ----------------
__global__ void prep_kernel(const float* __restrict__ x,
                            const float* __restrict__ g,
                            const float* __restrict__ b,
                            __half* __restrict__ o,
                            const float* __restrict__ rw,
                            const float* __restrict__ rb,
                            const float* __restrict__ wqkv, const float* __restrict__ wo,
                            const float* __restrict__ w1,   const float* __restrict__ w2)
{
    if (blockIdx.x >= TOK/8) {
        size_t off = ((size_t)(blockIdx.x - TOK/8)*256 + threadIdx.x) * 4;
        if (off >= W_TOTAL) return;
        const float* src;
        if (off < W_O_OFF)      src = wqkv + off;
        else if (off < W1_OFF)  src = wo + (off - W_O_OFF);
        else if (off < W2_OFF)  src = w1 + (off - W1_OFF);
        else                    src = w2 + (off - W2_OFF);
        float4 v = *(const float4*)src;
        *(uint2*)(g_wh + off) = make_uint2(packh2(v.x, v.y), packh2(v.z, v.w));
        return;
    }
    int lane = threadIdx.x & 31, warp = threadIdx.x >> 5;
    int row = blockIdx.x * 8 + warp;
    const float* xr = x + (size_t)row * DD;
    float4 v[4];
    float s = 0.f, q = 0.f;
    float lg0=0.f, lg1=0.f, lg2=0.f, lg3=0.f;
    #pragma unroll
    for (int i = 0; i < 4; i++) {
        int c0 = (i*32 + lane)*4;
        v[i] = *(const float4*)(xr + c0);
        s += v[i].x + v[i].y + v[i].z + v[i].w;
        q += v[i].x*v[i].x + v[i].y*v[i].y + v[i].z*v[i].z + v[i].w*v[i].w;
        #pragma unroll
        for (int j = 0; j < 4; j++) {
            float xv = (&v[i].x)[j];
            float4 r4 = *(const float4*)(rw + (c0 + j)*4);
            lg0 += xv*r4.x; lg1 += xv*r4.y; lg2 += xv*r4.z; lg3 += xv*r4.w;
        }
    }
    #pragma unroll
    for (int off = 16; off > 0; off >>= 1) {
        s += __shfl_xor_sync(0xffffffffu, s, off);
        q += __shfl_xor_sync(0xffffffffu, q, off);
        lg0 += __shfl_xor_sync(0xffffffffu, lg0, off);
        lg1 += __shfl_xor_sync(0xffffffffu, lg1, off);
        lg2 += __shfl_xor_sync(0xffffffffu, lg2, off);
        lg3 += __shfl_xor_sync(0xffffffffu, lg3, off);
    }
    if (lane == 0) {
        float l[4] = {lg0 + rb[0], lg1 + rb[1], lg2 + rb[2], lg3 + rb[3]};
        float mx = fmaxf(fmaxf(l[0], l[1]), fmaxf(l[2], l[3]));
        float p[4]; float Z = 0.f;
        #pragma unroll
        for (int e = 0; e < 4; e++) { p[e] = expf(l[e] - mx); Z += p[e]; }
        float inv = 1.f/Z;
        *(float4*)(g_probs + row*4) = make_float4(p[0]*inv, p[1]*inv, p[2]*inv, p[3]*inv);
    }
    float mu = s * (1.f/DD);
    float var = q * (1.f/DD) - mu*mu;
    float rstd = rsqrtf(var + 1e-5f);
    __half* orow = o + (size_t)row * DD;
    #pragma unroll
    for (int i = 0; i < 4; i++) {
        int idx = (i*32 + lane)*4;
        float4 gv = *(const float4*)(g + idx);
        float4 bv = *(const float4*)(b + idx);
        float o0 = (v[i].x - mu)*rstd*gv.x + bv.x;
        float o1 = (v[i].y - mu)*rstd*gv.y + bv.y;
        float o2 = (v[i].z - mu)*rstd*gv.z + bv.z;
        float o3 = (v[i].w - mu)*rstd*gv.w + bv.w;
        *(uint2*)(orow + idx) = make_uint2(packh2(o0, o1), packh2(o2, o3));
    }
}

// ---------------- plain layernorm (sorted order, LN2), warp per row ----------------
__global__ void ln_kernel(const float* __restrict__ x,
                          const float* __restrict__ g,
                          const float* __restrict__ b,
                          __half* __restrict__ o)
{
    int lane = threadIdx.x & 31, warp = threadIdx.x >> 5;
    int row = blockIdx.x * 8 + warp;
    const float* xr = x + (size_t)row * DD;
    float4 v[4];
    float s = 0.f, q = 0.f;
    #pragma unroll
    for (int i = 0; i < 4; i++) {
        v[i] = *(const float4*)(xr + (i*32 + lane)*4);
        s += v[i].x + v[i].y + v[i].z + v[i].w;
        q += v[i].x*v[i].x + v[i].y*v[i].y + v[i].z*v[i].z + v[i].w*v[i].w;
    }
    #pragma unroll
    for (int off = 16; off > 0; off >>= 1) {
        s += __shfl_xor_sync(0xffffffffu, s, off);
        q += __shfl_xor_sync(0xffffffffu, q, off);
    }
    float mu = s * (1.f/DD);
    float var = q * (1.f/DD) - mu*mu;
    float rstd = rsqrtf(var + 1e-5f);
    __half* orow = o + (size_t)row * DD;
    #pragma unroll
    for (int i = 0; i < 4; i++) {
        int idx = (i*32 + lane)*4;
        float4 gv = *(const float4*)(g + idx);
        float4 bv = *(const float4*)(b + idx);
        float o0 = (v[i].x - mu)*rstd*gv.x + bv.x;
        float o1 = (v[i].y - mu)*rstd*gv.y + bv.y;
        float o2 = (v[i].z - mu)*rstd*gv.z + bv.z;
        float o3 = (v[i].w - mu)*rstd*gv.w + bv.w;
        *(uint2*)(orow + idx) = make_uint2(packh2(o0, o1), packh2(o2, o3));
    }
}

// ---------------- parallel per-(b,e) sort, shuffle-bitonic ----------------
__global__ void sort_kernel()
{
    __shared__ unsigned long long keys[NN];
    int b = blockIdx.x >> 2, e = blockIdx.x & 3;
    int t = threadIdx.x;                      // 1024
    {
        unsigned pb0 = __float_as_uint(g_probs[(b*NN + 2*t)*4 + e]);
        unsigned pb1 = __float_as_uint(g_probs[(b*NN + 2*t + 1)*4 + e]);
        keys[2*t]   = ((unsigned long long)(~pb0) << 32) | (unsigned)(2*t);
        keys[2*t+1] = ((unsigned long long)(~pb1) << 32) | (unsigned)(2*t + 1);
    }
    __syncthreads();
    for (int k = 2; k <= NN; k <<= 1) {
        for (int j = k >> 1; j >= 64; j >>= 1) {
            #pragma unroll
            for (int w = 0; w < 2; w++) {
                int idx = t + w*1024;
                int l = idx ^ j;
                if (l > idx) {
                    bool asc = ((idx & k) == 0);
                    unsigned long long a = keys[idx], c2 = keys[l];
                    if ((a > c2) == asc) { keys[idx] = c2; keys[l] = a; }
                }
            }
            __syncthreads();
        }
        unsigned long long k0 = keys[2*t], k1 = keys[2*t+1];
        bool asc = ((2*t) & k) == 0;
        int jstart = (k >> 1) < 32 ? (k >> 1) : 32;
        for (int j = jstart; j >= 2; j >>= 1) {
            int hf = j >> 1;
            bool iless = ((t & hf) == 0);
            unsigned long long o0 = __shfl_xor_sync(0xffffffffu, k0, hf);
            unsigned long long o1 = __shfl_xor_sync(0xffffffffu, k1, hf);
            bool keepmin = (iless == asc);
            k0 = keepmin ? (k0 < o0 ? k0 : o0) : (k0 > o0 ? k0 : o0);
            k1 = keepmin ? (k1 < o1 ? k1 : o1) : (k1 > o1 ? k1 : o1);
        }
        {
            unsigned long long lo = k0 < k1 ? k0 : k1;
            unsigned long long hi = k0 < k1 ? k1 : k0;
            k0 = asc ? lo : hi;
            k1 = asc ? hi : lo;
        }
        keys[2*t] = k0; keys[2*t+1] = k1;
        __syncthreads();
    }
    g_sorted[(b*4+e)*NN + 2*t]   = (unsigned)(keys[2*t] & 0xFFFFFFFFull);
    g_sorted[(b*4+e)*NN + 2*t+1] = (unsigned)(keys[2*t+1] & 0xFFFFFFFFull);
}

// ---------------- claim: 512 threads, 4 tokens/thread, packed perm scan ----------------
__global__ void claim_kernel(float* __restrict__ out, int out_size)
{
    __shared__ int asg[NN];
    __shared__ int wsum[16];
    __shared__ unsigned long long wsum64[16];
    const int caps[4]  = {1024, 512, 256, 256};
    const int base4[4] = {0, 1024, 1536, 1792};
    int b = blockIdx.x, t = threadIdx.x;      // 512 threads
    int lane = t & 31, wid = t >> 5;          // 16 warps
    #pragma unroll
    for (int w = 0; w < 4; w++) asg[4*t + w] = -1;
    __syncthreads();

    for (int e = 3; e >= 0; e--) {
        int ids[4], f[4];
        int s = 0;
        #pragma unroll
        for (int w = 0; w < 4; w++) {
            ids[w] = (int)g_sorted[(b*4+e)*NN + 4*t + w];
            f[w] = (asg[ids[w]] < 0) ? 1 : 0;
            s += f[w];
        }
        int sc = s;
        #pragma unroll
        for (int o = 1; o < 32; o <<= 1) {
            int u = __shfl_up_sync(0xffffffff, sc, o);
            if (lane >= o) sc += u;
        }
        if (lane == 31) wsum[wid] = sc;
        __syncthreads();
        if (wid == 0 && lane < 16) {
            int w = wsum[lane];
            #pragma unroll
            for (int o = 1; o < 16; o <<= 1) {
                int u = __shfl_up_sync(0x0000ffffu, w, o);
                if (lane >= o) w += u;
            }
            wsum[lane] = w;
        }
        __syncthreads();
        int base = (wid > 0 ? wsum[wid-1] : 0) + (sc - s);
        int cap = caps[e];
        int run = 0;
        #pragma unroll
        for (int w = 0; w < 4; w++) {
            run += f[w];
            if (f[w] && (base + run) <= cap) asg[ids[w]] = e;
        }
        __syncthreads();
    }

    int a[4];
    unsigned long long pk = 0;
    #pragma unroll
    for (int w = 0; w < 4; w++) {
        a[w] = asg[4*t + w];
        pk += 1ull << (16 * a[w]);
    }
    unsigned long long sc64 = pk;
    #pragma unroll
    for (int o = 1; o < 32; o <<= 1) {
        unsigned long long u = __shfl_up_sync(0xffffffff, sc64, o);
        if (lane >= o) sc64 += u;
    }
    if (lane == 31) wsum64[wid] = sc64;
    __syncthreads();
    if (wid == 0 && lane < 16) {
        unsigned long long w = wsum64[lane];
        #pragma unroll
        for (int o = 1; o < 16; o <<= 1) {
            unsigned long long u = __shfl_up_sync(0x0000ffffu, w, o);
            if (lane >= o) w += u;
        }
        wsum64[lane] = w;
    }
    __syncthreads();
    unsigned long long base64 = (wid > 0 ? wsum64[wid-1] : 0ull) + (sc64 - pk);
    int cnt[4];
    #pragma unroll
    for (int e = 0; e < 4; e++) cnt[e] = (int)((base64 >> (16*e)) & 0xFFFF);
    #pragma unroll
    for (int w = 0; w < 4; w++) {
        int e = a[w];
        int gi = b*NN + 4*t + w;
        int pos = b*NN + base4[e] + cnt[e];
        cnt[e]++;
        g_perm[pos] = gi;
        g_rps[pos] = g_probs[gi*4 + e];
        if (out_size >= TOK*DD + TOK)   out[TOK*DD + gi] = (float)e;
        if (out_size >= TOK*DD + 2*TOK) out[TOK*DD + TOK + gi] = g_probs[gi*4 + e];
    }
}

// ---------------- fp16 GEMM, cp.async 4-stage, 128x128 tile, K-chunk 32, fused epilogues ----------------
__device__ __forceinline__ float gelu_t(float v) {
    float c = v*v*v;
    float t = tanhf(0.7978845608028654f*(v + 0.044715f*c));
    return 0.5f*v*(1.f+t);
}

#define ASTAGE 10240   /* 128*40*2 bytes */
#define BSTAGE 8704    /* 32*136*2 bytes */
#define GEMM_SMEM (4*(ASTAGE + BSTAGE))   /* 75776 */

// EPI 0: qkv (A row-gather via perm; output mask; skip empty col tiles)   Keff=d
// EPI 1: o-proj  z = x[perm] + mask*(c+b_o)                                Keff=d
// EPI 2: ff1 gelu (skip col tiles past 4d)                                 Keff=d
// EPI 3: ff2  out[perm] = z + gate*mask*(c+b2f)                            Keff=4d
template<int EPI>
__global__ void __launch_bounds__(256) tgemm_kernel(
                             const __half* __restrict__ A, const __half* __restrict__ B,
                             void* __restrict__ Cv, int N, int K,
                             const float* __restrict__ bias,
                             const float* __restrict__ add,
                             const float* __restrict__ alpha)
{
    int bx = blockIdx.x, by = blockIdx.y;
    int d = d_of_tile(by & 15);
    int col0 = bx * 128;
    int tid  = threadIdx.x;         // 256
    int lane = tid & 31;
    int warp = tid >> 5;

    if (EPI == 0) { if ((col0 & 511) >= d) return; }
    if (EPI == 2) { if (col0 >= 4*d) return; }
    if (EPI == 1 || EPI == 3) {
        if (col0 >= d) {
            int rr = tid >> 1;
            int cc = (tid & 1) * 64;
            int rg = by*128 + rr;
            int orig = g_perm[rg];
            const float* src = (EPI == 1) ? (add + (size_t)orig*N) : (add + (size_t)rg*N);
            float* dst = (EPI == 1) ? ((float*)Cv + (size_t)rg*N) : ((float*)Cv + (size_t)orig*N);
            #pragma unroll
            for (int j = 0; j < 64; j += 4)
                *(float4*)(dst + col0 + cc + j) = *(const float4*)(src + col0 + cc + j);
            return;
        }
    }
    int Keff = (EPI == 3) ? 4*d : d;
    int nIters = Keff >> 5;

    extern __shared__ __align__(16) char dynsm[];
    uint32_t asb = (uint32_t)__cvta_generic_to_shared(dynsm);
    uint32_t bsb = asb + 4*ASTAGE;

    int wm = warp >> 2, wn = warp & 3;
    float c[4][4][4];
    #pragma unroll
    for (int i=0;i<4;i++)
        #pragma unroll
        for (int j=0;j<4;j++)
            #pragma unroll
            for (int r=0;r<4;r++) c[i][j][r]=0.f;

    int ar  = tid >> 1;
    int ach = (tid & 1) * 16;
    int rowA0 = by*128 + ar;
    int rowA = (EPI == 0) ? g_perm[rowA0] : rowA0;
    const __half* Ag = A + (size_t)rowA*K + ach;
    int bk  = tid >> 3;
    int bn0 = (tid & 7) * 16;
    const __half* Bg = B + (size_t)bk*N + col0 + bn0;

    uint32_t aSlot = asb + ar*80 + ach*2;
    uint32_t bSlot = bsb + bk*272 + bn0*2;

    // prologue: up to 3 stages
    int inflight = 0;
    #pragma unroll
    for (int p = 0; p < 3; p++) {
        if (p < nIters) {
            const __half* Agp = Ag + p*32;
            const __half* Bgp = Bg + (size_t)(p*32)*N;
            cp_async16(aSlot + p*ASTAGE, Agp);
            cp_async16(aSlot + p*ASTAGE + 16, Agp + 8);
            cp_async16(bSlot + p*BSTAGE, Bgp);
            cp_async16(bSlot + p*BSTAGE + 16, Bgp + 8);
            cp_commit();
            inflight++;
        }
    }

    int st = 0;
    for (int it = 0; it < nIters; it++) {
        cp_waitg(inflight - 1);
        inflight--;
        __syncthreads();
        if (it + 3 < nIters) {
            int sn = st + 3; if (sn >= 4) sn -= 4;
            const __half* Agn = Ag + (it + 3)*32;
            const __half* Bgn = Bg + (size_t)((it + 3)*32)*N;
            cp_async16(aSlot + sn*ASTAGE, Agn);
            cp_async16(aSlot + sn*ASTAGE + 16, Agn + 8);
            cp_async16(bSlot + sn*BSTAGE, Bgn);
            cp_async16(bSlot + sn*BSTAGE + 16, Bgn + 8);
            cp_commit();
            inflight++;
        }
        uint32_t ab = asb + st*ASTAGE;
        uint32_t bb = bsb + st*BSTAGE;
        #pragma unroll
        for (int kk = 0; kk < 32; kk += 16) {
            uint32_t af[4][4];
            #pragma unroll
            for (int am = 0; am < 4; am++) {
                int m = lane >> 3;
                int row = wm*64 + am*16 + (lane & 7) + (m & 1)*8;
                int col = kk + (m >> 1)*8;
                ldsm_x4(af[am][0], af[am][1], af[am][2], af[am][3], ab + row*80 + col*2);
            }
            #pragma unroll
            for (int an = 0; an < 4; an++) {
                int brow = kk + (lane & 15);
                int bcol = wn*32 + an*8;
                uint32_t b0, b1;
                ldsm_x2t(b0, b1, bb + brow*272 + bcol*2);
                #pragma unroll
                for (int am = 0; am < 4; am++)
                    mma_f16(c[am][an], af[am], b0, b1);
            }
        }
        st++; if (st >= 4) st -= 4;
    }

    float aval = (EPI == 3) ? alpha[0] : 0.f;
    #pragma unroll
    for (int am = 0; am < 4; am++) {
        int r0 = by*128 + wm*64 + am*16 + (lane>>2);
        int r1 = r0 + 8;
        float gate0 = (EPI == 3) ? (aval * g_rps[r0] + 1.f) : 0.f;
        float gate1 = (EPI == 3) ? (aval * g_rps[r1] + 1.f) : 0.f;
        int org0 = (EPI == 1 || EPI == 3) ? g_perm[r0] : 0;
        int org1 = (EPI == 1 || EPI == 3) ? g_perm[r1] : 0;
        #pragma unroll
        for (int an = 0; an < 4; an++) {
            int col = col0 + wn*32 + an*8 + (lane&3)*2;
            #pragma unroll
            for (int h2 = 0; h2 < 2; h2++) {
                int r = h2 ? r1 : r0;
                int org = h2 ? org1 : org0;
                float gate = h2 ? gate1 : gate0;
                float v0 = c[am][an][2*h2], v1 = c[am][an][2*h2+1];
                if (EPI == 0) {
                    float o0 = ((col & 511) < d)     ? v0 : 0.f;
                    float o1 = (((col+1) & 511) < d) ? v1 : 0.f;
                    *(uint32_t*)((__half*)Cv + (size_t)r*N + col) = packh2(o0, o1);
                } else if (EPI == 1) {
                    size_t xi = (size_t)org*N + col;
                    float o0 = add[xi]   + ((col   < d) ? (v0 + bias[col])   : 0.f);
                    float o1 = add[xi+1] + ((col+1 < d) ? (v1 + bias[col+1]) : 0.f);
                    *(float2*)((float*)Cv + (size_t)r*N + col) = make_float2(o0, o1);
                } else if (EPI == 2) {
                    float o0 = gelu_t(v0 + bias[col]);
                    float o1 = gelu_t(v1 + bias[col+1]);
                    *(uint32_t*)((__half*)Cv + (size_t)r*N + col) = packh2(o0, o1);
                } else {
                    size_t zi = (size_t)r*N + col;
                    float z0 = (col   < d) ? (v0 + bias[col])   : 0.f;
                    float z1 = (col+1 < d) ? (v1 + bias[col+1]) : 0.f;
                    float o0 = add[zi]   + gate * z0;
                    float o1 = add[zi+1] + gate * z1;
                    *(float2*)((float*)Cv + (size_t)org*N + col) = make_float2(o0, o1);
                }
            }
        }
    }
}

// ---------------- fp16 flash attention, intra-block split-K (2 groups) ----------------
#define QS_OFF 0
#define KS_OFF(g) (4608 + (g)*4608)
#define VS_OFF(g) (13824 + (g)*4608)

__global__ void attn_kernel()   // 256 threads = 2 warp-groups of 4 warps
{
    __shared__ __align__(16) __half sm[23040];

    int b = blockIdx.y;
    int qi = blockIdx.x;            // 0..79
    int h, qt;
    if (qi < 32)      { h = 0; qt = qi; }
    else if (qi < 48) { h = 1; qt = 16 + (qi - 32); }
    else if (qi < 56) { h = 2; qt = 24 + (qi - 48); }
    else if (qi < 64) { h = 3; qt = 24 + (qi - 56); }
    else              { h = 4 + ((qi - 64) >> 2); qt = 28 + ((qi - 64) & 3); }
    int kt0 = (h == 0) ? 0 : (h == 1) ? 16 : (h < 4) ? 24 : 28;
    int nz = kt0 * 64;

    int tid = threadIdx.x;
    int lane = tid & 31;
    int warp = tid >> 5;
    int grp = warp >> 2;            // 0/1
    int w4 = warp & 3;
    int ltid = tid & 127;

    int half = (32 - kt0) >> 1;
    int ktbeg = kt0 + grp*half;

    __half* Qs = sm + QS_OFF;
    __half* Ks = sm + KS_OFF(grp);
    __half* Vs = sm + VS_OFF(grp);
    uint32_t vsb = (uint32_t)__cvta_generic_to_shared(Vs);

    const __half* qb = g_qkv + (size_t)(b*NN + qt*64)*1536 + h*64;
    for (int i = tid; i < 512; i += 256) {
        int n = i >> 3, c8 = (i & 7) * 8;
        *(uint4*)(&Qs[n*72 + c8]) = *(const uint4*)(qb + (size_t)n*1536 + c8);
    }
    __syncthreads();

    uint32_t qf[4][4];
    {
        int r = w4*16 + (lane >> 2);
        #pragma unroll
        for (int ka = 0; ka < 4; ka++) {
            int cc = ka*16 + (lane & 3)*2;
            qf[ka][0] = *(const uint32_t*)(&Qs[r*72 + cc]);
            qf[ka][1] = *(const uint32_t*)(&Qs[(r+8)*72 + cc]);
            qf[ka][2] = *(const uint32_t*)(&Qs[r*72 + cc + 8]);
            qf[ka][3] = *(const uint32_t*)(&Qs[(r+8)*72 + cc + 8]);
        }
    }

    float o[8][4];
    #pragma unroll
    for (int i=0;i<8;i++)
        #pragma unroll
        for (int j=0;j<4;j++) o[i][j]=0.f;
    float m0, m1, l0, l1;
    if (grp == 0 && nz > 0) { m0 = 0.f; m1 = 0.f; l0 = (float)nz; l1 = (float)nz; }
    else                    { m0 = -1e30f; m1 = -1e30f; l0 = 0.f; l1 = 0.f; }

    for (int ii = 0; ii < half; ii++) {
        int kt = ktbeg + ii;
        __syncthreads();
        const __half* kb = g_qkv + (size_t)(b*NN + kt*64)*1536 + 512 + h*64;
        for (int i = ltid; i < 512; i += 128) {
            int n = i >> 3, c8 = (i & 7) * 8;
            *(uint4*)(&Ks[n*72 + c8]) = *(const uint4*)(kb + (size_t)n*1536 + c8);
            *(uint4*)(&Vs[n*72 + c8]) = *(const uint4*)(kb + 512 + (size_t)n*1536 + c8);
        }
        __syncthreads();

        float s[8][4];
        #pragma unroll
        for (int i=0;i<8;i++)
            #pragma unroll
            for (int j=0;j<4;j++) s[i][j]=0.f;
        #pragma unroll
        for (int ka = 0; ka < 4; ka++) {
            #pragma unroll
            for (int na = 0; na < 8; na++) {
                int n = na*8 + (lane >> 2);
                int k = ka*16 + (lane & 3)*2;
                uint32_t b0 = *(const uint32_t*)(&Ks[n*72 + k]);
                uint32_t b1 = *(const uint32_t*)(&Ks[n*72 + k + 8]);
                mma_f16(s[na], qf[ka], b0, b1);
            }
        }

        float mx0 = -1e30f, mx1 = -1e30f;
        #pragma unroll
        for (int na = 0; na < 8; na++) {
            s[na][0]*=0.125f; s[na][1]*=0.125f; s[na][2]*=0.125f; s[na][3]*=0.125f;
            mx0 = fmaxf(mx0, fmaxf(s[na][0], s[na][1]));
            mx1 = fmaxf(mx1, fmaxf(s[na][2], s[na][3]));
        }
        mx0 = fmaxf(mx0, __shfl_xor_sync(0xffffffffu, mx0, 1));
        mx0 = fmaxf(mx0, __shfl_xor_sync(0xffffffffu, mx0, 2));
        mx1 = fmaxf(mx1, __shfl_xor_sync(0xffffffffu, mx1, 1));
        mx1 = fmaxf(mx1, __shfl_xor_sync(0xffffffffu, mx1, 2));
        float mn0 = fmaxf(m0, mx0), mn1 = fmaxf(m1, mx1);
        float sc0 = __expf(m0 - mn0), sc1 = __expf(m1 - mn1);
        m0 = mn0; m1 = mn1;

        float sum0 = 0.f, sum1 = 0.f;
        #pragma unroll
        for (int na = 0; na < 8; na++) {
            s[na][0] = __expf(s[na][0] - m0);
            s[na][1] = __expf(s[na][1] - m0);
            s[na][2] = __expf(s[na][2] - m1);
            s[na][3] = __expf(s[na][3] - m1);
            sum0 += s[na][0] + s[na][1];
            sum1 += s[na][2] + s[na][3];
        }
        sum0 += __shfl_xor_sync(0xffffffffu, sum0, 1);
        sum0 += __shfl_xor_sync(0xffffffffu, sum0, 2);
        sum1 += __shfl_xor_sync(0xffffffffu, sum1, 1);
        sum1 += __shfl_xor_sync(0xffffffffu, sum1, 2);
        l0 = l0*sc0 + sum0;
        l1 = l1*sc1 + sum1;

        #pragma unroll
        for (int da = 0; da < 8; da++) {
            o[da][0]*=sc0; o[da][1]*=sc0; o[da][2]*=sc1; o[da][3]*=sc1;
        }

        #pragma unroll
        for (int ka = 0; ka < 4; ka++) {
            uint32_t pa[4];
            pa[0] = packh2(s[2*ka][0],   s[2*ka][1]);
            pa[1] = packh2(s[2*ka][2],   s[2*ka][3]);
            pa[2] = packh2(s[2*ka+1][0], s[2*ka+1][1]);
            pa[3] = packh2(s[2*ka+1][2], s[2*ka+1][3]);
            uint32_t rowaddr = vsb + (ka*16 + (lane & 15))*144;
            #pragma unroll
            for (int da = 0; da < 8; da++) {
                uint32_t b0, b1;
                ldsm_x2t(b0, b1, rowaddr + da*16);
                mma_f16(o[da], pa, b0, b1);
            }
        }
    }

    __syncthreads();
    float* so = (float*)sm;
    float* sml = so + 64*66;
    int r0 = w4*16 + (lane >> 2);
    int r1 = r0 + 8;
    if (grp == 1) {
        #pragma unroll
        for (int da = 0; da < 8; da++) {
            int col = da*8 + (lane&3)*2;
            *(float2*)(&so[r0*66 + col]) = make_float2(o[da][0], o[da][1]);
            *(float2*)(&so[r1*66 + col]) = make_float2(o[da][2], o[da][3]);
        }
        if ((lane & 3) == 0) {
            sml[r0] = m0; sml[64 + r0] = l0;
            sml[r1] = m1; sml[64 + r1] = l1;
        }
    }
    __syncthreads();
    if (grp == 0) {
        float m1s0 = sml[r0], l1s0 = sml[64 + r0];
        float m1s1 = sml[r1], l1s1 = sml[64 + r1];
        float M0 = fmaxf(m0, m1s0), M1 = fmaxf(m1, m1s1);
        float a0 = __expf(m0 - M0), b0s = __expf(m1s0 - M0);
        float a1 = __expf(m1 - M1), b1s = __expf(m1s1 - M1);
        float L0 = l0*a0 + l1s0*b0s;
        float L1 = l1*a1 + l1s1*b1s;
        float inv0 = 1.f / L0, inv1 = 1.f / L1;
        int tok0 = b*NN + qt*64 + r0;
        int tok1 = tok0 + 8;
        #pragma unroll
        for (int da = 0; da < 8; da++) {
            int col = da*8 + (lane&3)*2;
            float2 p0 = *(float2*)(&so[r0*66 + col]);
            float2 p1 = *(float2*)(&so[r1*66 + col]);
            float f00 = (o[da][0]*a0 + p0.x*b0s) * inv0;
            float f01 = (o[da][1]*a0 + p0.y*b0s) * inv0;
            float f10 = (o[da][2]*a1 + p1.x*b1s) * inv1;
            float f11 = (o[da][3]*a1 + p1.y*b1s) * inv1;
            int gcol = h*64 + col;
            *(uint32_t*)(g_o + (size_t)tok0*DD + gcol) = packh2(f00, f01);
            *(uint32_t*)(g_o + (size_t)tok1*DD + gcol) = packh2(f10, f11);
        }
    }
}

// ---------------- launcher ----------------
extern "C" void kernel_launch(void* const* d_in, const int* in_sizes, int n_in,
                              void* d_out, int out_size)
{
    const float* x     = (const float*)d_in[0];
    const float* r_w   = (const float*)d_in[1];
    const float* r_b   = (const float*)d_in[2];
    const float* g1    = (const float*)d_in[3];
    const float* b1    = (const float*)d_in[4];
    const float* g2    = (const float*)d_in[5];
    const float* b2    = (const float*)d_in[6];
    const float* w_qkv = (const float*)d_in[7];
    const float* w_o   = (const float*)d_in[8];
    const float* b_o   = (const float*)d_in[9];
    const float* w1    = (const float*)d_in[10];
    const float* b1f   = (const float*)d_in[11];
    const float* w2    = (const float*)d_in[12];
    const float* b2f   = (const float*)d_in[13];
    const float* alpha = (const float*)d_in[14];
    float* out = (float*)d_out;

    __half *p_h, *p_qkv, *p_o, *p_hid, *p_wh;
    float *p_z;
    cudaGetSymbolAddress((void**)&p_h,   g_h);
    cudaGetSymbolAddress((void**)&p_qkv, g_qkv);
    cudaGetSymbolAddress((void**)&p_o,   g_o);
    cudaGetSymbolAddress((void**)&p_z,   g_z);
    cudaGetSymbolAddress((void**)&p_hid, g_hid);
    cudaGetSymbolAddress((void**)&p_wh,  g_wh);

    cudaFuncSetAttribute(tgemm_kernel<0>, cudaFuncAttributeMaxDynamicSharedMemorySize, GEMM_SMEM);
    cudaFuncSetAttribute(tgemm_kernel<1>, cudaFuncAttributeMaxDynamicSharedMemorySize, GEMM_SMEM);
    cudaFuncSetAttribute(tgemm_kernel<2>, cudaFuncAttributeMaxDynamicSharedMemorySize, GEMM_SMEM);
    cudaFuncSetAttribute(tgemm_kernel<3>, cudaFuncAttributeMaxDynamicSharedMemorySize, GEMM_SMEM);

    // LN1 + router + weight conversion (fused)
    prep_kernel<<<TOK/8 + (W_TOTAL/4 + 255)/256, 256>>>(x, g1, b1, p_h, r_w, r_b,
                                                        w_qkv, w_o, w1, w2);
    sort_kernel<<<BB*EE, 1024>>>();
    claim_kernel<<<BB, 512>>>(out, out_size);

    // attention path
    tgemm_kernel<0><<<dim3(1536/128, TOK/128), 256, GEMM_SMEM>>>(p_h, p_wh + W_QKV_OFF, p_qkv, 1536, 512,
                                                                 nullptr, nullptr, nullptr);
    attn_kernel<<<dim3(80, BB), 256>>>();
    tgemm_kernel<1><<<dim3(512/128, TOK/128), 256, GEMM_SMEM>>>(p_o, p_wh + W_O_OFF, p_z, 512, 512,
                                                                b_o, x, nullptr);

    // feed-forward path
    ln_kernel<<<TOK/8, 256>>>(p_z, g2, b2, p_h);
    tgemm_kernel<2><<<dim3(2048/128, TOK/128), 256, GEMM_SMEM>>>(p_h, p_wh + W1_OFF, p_hid, 2048, 512,
                                                                 b1f, nullptr, nullptr);
    tgemm_kernel<3><<<dim3(512/128, TOK/128), 256, GEMM_SMEM>>>(p_hid, p_wh + W2_OFF, out, 512, 2048,
                                                                b2f, p_z, alpha);
}

// round 16
// speedup vs baseline: 1.1201x; 1.0076x over previous
#include <cuda_runtime.h>
#include <cuda_fp16.h>
#include <math.h>
#include <stdint.h>

#define BB 4
#define NN 2048
#define DD 512
#define HH 8
#define EE 4
#define RR 4
#define TOK (BB*NN)      /* 8192 */
#define HID (RR*DD)      /* 2048 */

// weight fp16 cache offsets (halves)
#define W_QKV_OFF 0
#define W_O_OFF   786432
#define W1_OFF    1048576
#define W2_OFF    2097152
#define W_TOTAL   3145728

// ---------------- scratch ----------------
__device__ float g_probs[TOK*EE];
__device__ unsigned g_sorted[BB*EE*NN];
__device__ int    g_perm[TOK];
__device__ float  g_rps[TOK];
__device__ __align__(16) __half g_wh[W_TOTAL];
__device__ __align__(16) __half g_h[TOK*DD];
__device__ __align__(16) __half g_qkv[TOK*3*DD];
__device__ __align__(16) __half g_o[TOK*DD];
__device__ __align__(16) float  g_z[TOK*DD];
__device__ __align__(16) __half g_hid[(size_t)TOK*HID];

__device__ __forceinline__ int d_of_tile(int tb) {
    return tb < 8 ? 64 : tb < 12 ? 128 : tb < 14 ? 256 : 512;
}
// LPT remap: heavy tiles (d=512) first in launch order
__device__ __forceinline__ int remap_tile(int by) {
    int t = by & 15;
    t = (t < 2) ? t + 14 : (t < 4) ? t + 10 : (t < 8) ? t + 4 : t - 8;
    return (by & ~15) | t;
}

// ---------------- helpers ----------------
// non-volatile: register data-deps preserve math order; ptxas may software-pipeline
__device__ __forceinline__ void mma_f16(float* d, const uint32_t* a, uint32_t b0, uint32_t b1) {
    asm("mma.sync.aligned.m16n8k16.row.col.f32.f16.f16.f32 "
        "{%0,%1,%2,%3}, {%4,%5,%6,%7}, {%8,%9}, {%0,%1,%2,%3};\n"
        : "+f"(d[0]), "+f"(d[1]), "+f"(d[2]), "+f"(d[3])
        : "r"(a[0]), "r"(a[1]), "r"(a[2]), "r"(a[3]), "r"(b0), "r"(b1));
}
// non-volatile + memory clobber: ordered vs barriers/cp.async, schedulable vs mma
__device__ __forceinline__ void ldsm_x4(uint32_t& r0, uint32_t& r1, uint32_t& r2, uint32_t& r3, uint32_t addr) {
    asm("ldmatrix.sync.aligned.m8n8.x4.shared.b16 {%0,%1,%2,%3}, [%4];"
        : "=r"(r0), "=r"(r1), "=r"(r2), "=r"(r3) : "r"(addr) : "memory");
}
__device__ __forceinline__ void ldsm_x2t(uint32_t& r0, uint32_t& r1, uint32_t addr) {
    asm("ldmatrix.sync.aligned.m8n8.x2.trans.shared.b16 {%0,%1}, [%2];"
        : "=r"(r0), "=r"(r1) : "r"(addr) : "memory");
}
__device__ __forceinline__ uint32_t packh2(float a, float b) {
    __half2 h = __floats2half2_rn(a, b);
    return *(uint32_t*)&h;
}
__device__ __forceinline__ void cp_async16(uint32_t saddr, const void* gaddr) {
    asm volatile("cp.async.ca.shared.global [%0], [%1], 16;\n" :: "r"(saddr), "l"(gaddr));
}
__device__ __forceinline__ void cp_commit() {
    asm volatile("cp.async.commit_group;\n" ::: "memory");
}
__device__ __forceinline__ void cp_waitg(int n) {
    if (n <= 0)      asm volatile("cp.async.wait_group 0;\n" ::: "memory");
    else if (n == 1) asm volatile("cp.async.wait_group 1;\n" ::: "memory");
    else             asm volatile("cp.async.wait_group 2;\n" ::: "memory");
}

// ---------------- prep: LN1 + router (blocks 0..1023) fused with wconv (blocks 1024..4095) ----------------
__global__ void prep_kernel(const float* __restrict__ x,
                            const float* __restrict__ g,
                            const float* __restrict__ b,
                            __half* __restrict__ o,
                            const float* __restrict__ rw,
                            const float* __restrict__ rb,
                            const float* __restrict__ wqkv, const float* __restrict__ wo,
                            const float* __restrict__ w1,   const float* __restrict__ w2)
{
    if (blockIdx.x >= TOK/8) {
        size_t off = ((size_t)(blockIdx.x - TOK/8)*256 + threadIdx.x) * 4;
        if (off >= W_TOTAL) return;
        const float* src;
        if (off < W_O_OFF)      src = wqkv + off;
        else if (off < W1_OFF)  src = wo + (off - W_O_OFF);
        else if (off < W2_OFF)  src = w1 + (off - W1_OFF);
        else                    src = w2 + (off - W2_OFF);
        float4 v = *(const float4*)src;
        *(uint2*)(g_wh + off) = make_uint2(packh2(v.x, v.y), packh2(v.z, v.w));
        return;
    }
    int lane = threadIdx.x & 31, warp = threadIdx.x >> 5;
    int row = blockIdx.x * 8 + warp;
    const float* xr = x + (size_t)row * DD;
    float4 v[4];
    float s = 0.f, q = 0.f;
    float lg0=0.f, lg1=0.f, lg2=0.f, lg3=0.f;
    #pragma unroll
    for (int i = 0; i < 4; i++) {
        int c0 = (i*32 + lane)*4;
        v[i] = *(const float4*)(xr + c0);
        s += v[i].x + v[i].y + v[i].z + v[i].w;
        q += v[i].x*v[i].x + v[i].y*v[i].y + v[i].z*v[i].z + v[i].w*v[i].w;
        #pragma unroll
        for (int j = 0; j < 4; j++) {
            float xv = (&v[i].x)[j];
            float4 r4 = *(const float4*)(rw + (c0 + j)*4);
            lg0 += xv*r4.x; lg1 += xv*r4.y; lg2 += xv*r4.z; lg3 += xv*r4.w;
        }
    }
    #pragma unroll
    for (int off = 16; off > 0; off >>= 1) {
        s += __shfl_xor_sync(0xffffffffu, s, off);
        q += __shfl_xor_sync(0xffffffffu, q, off);
        lg0 += __shfl_xor_sync(0xffffffffu, lg0, off);
        lg1 += __shfl_xor_sync(0xffffffffu, lg1, off);
        lg2 += __shfl_xor_sync(0xffffffffu, lg2, off);
        lg3 += __shfl_xor_sync(0xffffffffu, lg3, off);
    }
    if (lane == 0) {
        float l[4] = {lg0 + rb[0], lg1 + rb[1], lg2 + rb[2], lg3 + rb[3]};
        float mx = fmaxf(fmaxf(l[0], l[1]), fmaxf(l[2], l[3]));
        float p[4]; float Z = 0.f;
        #pragma unroll
        for (int e = 0; e < 4; e++) { p[e] = expf(l[e] - mx); Z += p[e]; }
        float inv = 1.f/Z;
        *(float4*)(g_probs + row*4) = make_float4(p[0]*inv, p[1]*inv, p[2]*inv, p[3]*inv);
    }
    float mu = s * (1.f/DD);
    float var = q * (1.f/DD) - mu*mu;
    float rstd = rsqrtf(var + 1e-5f);
    __half* orow = o + (size_t)row * DD;
    #pragma unroll
    for (int i = 0; i < 4; i++) {
        int idx = (i*32 + lane)*4;
        float4 gv = *(const float4*)(g + idx);
        float4 bv = *(const float4*)(b + idx);
        float o0 = (v[i].x - mu)*rstd*gv.x + bv.x;
        float o1 = (v[i].y - mu)*rstd*gv.y + bv.y;
        float o2 = (v[i].z - mu)*rstd*gv.z + bv.z;
        float o3 = (v[i].w - mu)*rstd*gv.w + bv.w;
        *(uint2*)(orow + idx) = make_uint2(packh2(o0, o1), packh2(o2, o3));
    }
}

// ---------------- plain layernorm (sorted order, LN2), warp per row ----------------
__global__ void ln_kernel(const float* __restrict__ x,
                          const float* __restrict__ g,
                          const float* __restrict__ b,
                          __half* __restrict__ o)
{
    int lane = threadIdx.x & 31, warp = threadIdx.x >> 5;
    int row = blockIdx.x * 8 + warp;
    const float* xr = x + (size_t)row * DD;
    float4 v[4];
    float s = 0.f, q = 0.f;
    #pragma unroll
    for (int i = 0; i < 4; i++) {
        v[i] = *(const float4*)(xr + (i*32 + lane)*4);
        s += v[i].x + v[i].y + v[i].z + v[i].w;
        q += v[i].x*v[i].x + v[i].y*v[i].y + v[i].z*v[i].z + v[i].w*v[i].w;
    }
    #pragma unroll
    for (int off = 16; off > 0; off >>= 1) {
        s += __shfl_xor_sync(0xffffffffu, s, off);
        q += __shfl_xor_sync(0xffffffffu, q, off);
    }
    float mu = s * (1.f/DD);
    float var = q * (1.f/DD) - mu*mu;
    float rstd = rsqrtf(var + 1e-5f);
    __half* orow = o + (size_t)row * DD;
    #pragma unroll
    for (int i = 0; i < 4; i++) {
        int idx = (i*32 + lane)*4;
        float4 gv = *(const float4*)(g + idx);
        float4 bv = *(const float4*)(b + idx);
        float o0 = (v[i].x - mu)*rstd*gv.x + bv.x;
        float o1 = (v[i].y - mu)*rstd*gv.y + bv.y;
        float o2 = (v[i].z - mu)*rstd*gv.z + bv.z;
        float o3 = (v[i].w - mu)*rstd*gv.w + bv.w;
        *(uint2*)(orow + idx) = make_uint2(packh2(o0, o1), packh2(o2, o3));
    }
}

// ---------------- parallel per-(b,e) sort, shuffle-bitonic ----------------
__global__ void sort_kernel()
{
    __shared__ unsigned long long keys[NN];
    int b = blockIdx.x >> 2, e = blockIdx.x & 3;
    int t = threadIdx.x;                      // 1024
    {
        unsigned pb0 = __float_as_uint(g_probs[(b*NN + 2*t)*4 + e]);
        unsigned pb1 = __float_as_uint(g_probs[(b*NN + 2*t + 1)*4 + e]);
        keys[2*t]   = ((unsigned long long)(~pb0) << 32) | (unsigned)(2*t);
        keys[2*t+1] = ((unsigned long long)(~pb1) << 32) | (unsigned)(2*t + 1);
    }
    __syncthreads();
    for (int k = 2; k <= NN; k <<= 1) {
        for (int j = k >> 1; j >= 64; j >>= 1) {
            #pragma unroll
            for (int w = 0; w < 2; w++) {
                int idx = t + w*1024;
                int l = idx ^ j;
                if (l > idx) {
                    bool asc = ((idx & k) == 0);
                    unsigned long long a = keys[idx], c2 = keys[l];
                    if ((a > c2) == asc) { keys[idx] = c2; keys[l] = a; }
                }
            }
            __syncthreads();
        }
        unsigned long long k0 = keys[2*t], k1 = keys[2*t+1];
        bool asc = ((2*t) & k) == 0;
        int jstart = (k >> 1) < 32 ? (k >> 1) : 32;
        for (int j = jstart; j >= 2; j >>= 1) {
            int hf = j >> 1;
            bool iless = ((t & hf) == 0);
            unsigned long long o0 = __shfl_xor_sync(0xffffffffu, k0, hf);
            unsigned long long o1 = __shfl_xor_sync(0xffffffffu, k1, hf);
            bool keepmin = (iless == asc);
            k0 = keepmin ? (k0 < o0 ? k0 : o0) : (k0 > o0 ? k0 : o0);
            k1 = keepmin ? (k1 < o1 ? k1 : o1) : (k1 > o1 ? k1 : o1);
        }
        {
            unsigned long long lo = k0 < k1 ? k0 : k1;
            unsigned long long hi = k0 < k1 ? k1 : k0;
            k0 = asc ? lo : hi;
            k1 = asc ? hi : lo;
        }
        keys[2*t] = k0; keys[2*t+1] = k1;
        __syncthreads();
    }
    g_sorted[(b*4+e)*NN + 2*t]   = (unsigned)(keys[2*t] & 0xFFFFFFFFull);
    g_sorted[(b*4+e)*NN + 2*t+1] = (unsigned)(keys[2*t+1] & 0xFFFFFFFFull);
}

// ---------------- claim: 512 threads, 4 tokens/thread, packed perm scan ----------------
__global__ void claim_kernel(float* __restrict__ out, int out_size)
{
    __shared__ int asg[NN];
    __shared__ int wsum[16];
    __shared__ unsigned long long wsum64[16];
    const int caps[4]  = {1024, 512, 256, 256};
    const int base4[4] = {0, 1024, 1536, 1792};
    int b = blockIdx.x, t = threadIdx.x;      // 512 threads
    int lane = t & 31, wid = t >> 5;          // 16 warps
    #pragma unroll
    for (int w = 0; w < 4; w++) asg[4*t + w] = -1;
    __syncthreads();

    for (int e = 3; e >= 0; e--) {
        int ids[4], f[4];
        int s = 0;
        #pragma unroll
        for (int w = 0; w < 4; w++) {
            ids[w] = (int)g_sorted[(b*4+e)*NN + 4*t + w];
            f[w] = (asg[ids[w]] < 0) ? 1 : 0;
            s += f[w];
        }
        int sc = s;
        #pragma unroll
        for (int o = 1; o < 32; o <<= 1) {
            int u = __shfl_up_sync(0xffffffff, sc, o);
            if (lane >= o) sc += u;
        }
        if (lane == 31) wsum[wid] = sc;
        __syncthreads();
        if (wid == 0 && lane < 16) {
            int w = wsum[lane];
            #pragma unroll
            for (int o = 1; o < 16; o <<= 1) {
                int u = __shfl_up_sync(0x0000ffffu, w, o);
                if (lane >= o) w += u;
            }
            wsum[lane] = w;
        }
        __syncthreads();
        int base = (wid > 0 ? wsum[wid-1] : 0) + (sc - s);
        int cap = caps[e];
        int run = 0;
        #pragma unroll
        for (int w = 0; w < 4; w++) {
            run += f[w];
            if (f[w] && (base + run) <= cap) asg[ids[w]] = e;
        }
        __syncthreads();
    }

    int a[4];
    unsigned long long pk = 0;
    #pragma unroll
    for (int w = 0; w < 4; w++) {
        a[w] = asg[4*t + w];
        pk += 1ull << (16 * a[w]);
    }
    unsigned long long sc64 = pk;
    #pragma unroll
    for (int o = 1; o < 32; o <<= 1) {
        unsigned long long u = __shfl_up_sync(0xffffffff, sc64, o);
        if (lane >= o) sc64 += u;
    }
    if (lane == 31) wsum64[wid] = sc64;
    __syncthreads();
    if (wid == 0 && lane < 16) {
        unsigned long long w = wsum64[lane];
        #pragma unroll
        for (int o = 1; o < 16; o <<= 1) {
            unsigned long long u = __shfl_up_sync(0x0000ffffu, w, o);
            if (lane >= o) w += u;
        }
        wsum64[lane] = w;
    }
    __syncthreads();
    unsigned long long base64 = (wid > 0 ? wsum64[wid-1] : 0ull) + (sc64 - pk);
    int cnt[4];
    #pragma unroll
    for (int e = 0; e < 4; e++) cnt[e] = (int)((base64 >> (16*e)) & 0xFFFF);
    #pragma unroll
    for (int w = 0; w < 4; w++) {
        int e = a[w];
        int gi = b*NN + 4*t + w;
        int pos = b*NN + base4[e] + cnt[e];
        cnt[e]++;
        g_perm[pos] = gi;
        g_rps[pos] = g_probs[gi*4 + e];
        if (out_size >= TOK*DD + TOK)   out[TOK*DD + gi] = (float)e;
        if (out_size >= TOK*DD + 2*TOK) out[TOK*DD + TOK + gi] = g_probs[gi*4 + e];
    }
}

// ---------------- fp16 GEMM, cp.async 4-stage, 128x128 tile, LPT order, fused epilogues ----------------
__device__ __forceinline__ float gelu_t(float v) {
    float c = v*v*v;
    float t = tanhf(0.7978845608028654f*(v + 0.044715f*c));
    return 0.5f*v*(1.f+t);
}

#define ASTAGE 10240   /* 128*40*2 bytes */
#define BSTAGE 8704    /* 32*136*2 bytes */
#define GEMM_SMEM (4*(ASTAGE + BSTAGE))   /* 75776 */

// EPI 0: qkv (A row-gather via perm; output mask; skip empty col tiles)   Keff=d
// EPI 1: o-proj  z = x[perm] + mask*(c+b_o)                                Keff=d
// EPI 2: ff1 gelu (skip col tiles past 4d)                                 Keff=d
// EPI 3: ff2  out[perm] = z + gate*mask*(c+b2f)                            Keff=4d
template<int EPI>
__global__ void __launch_bounds__(256) tgemm_kernel(
                             const __half* __restrict__ A, const __half* __restrict__ B,
                             void* __restrict__ Cv, int N, int K,
                             const float* __restrict__ bias,
                             const float* __restrict__ add,
                             const float* __restrict__ alpha)
{
    int bx = blockIdx.x;
    int byr = remap_tile(blockIdx.y);     // LPT: heavy tiles first
    int d = d_of_tile(byr & 15);
    int col0 = bx * 128;
    int tid  = threadIdx.x;         // 256
    int lane = tid & 31;
    int warp = tid >> 5;

    if (EPI == 0) { if ((col0 & 511) >= d) return; }
    if (EPI == 2) { if (col0 >= 4*d) return; }
    if (EPI == 1 || EPI == 3) {
        if (col0 >= d) {
            int rr = tid >> 1;
            int cc = (tid & 1) * 64;
            int rg = byr*128 + rr;
            int orig = g_perm[rg];
            const float* src = (EPI == 1) ? (add + (size_t)orig*N) : (add + (size_t)rg*N);
            float* dst = (EPI == 1) ? ((float*)Cv + (size_t)rg*N) : ((float*)Cv + (size_t)orig*N);
            #pragma unroll
            for (int j = 0; j < 64; j += 4)
                *(float4*)(dst + col0 + cc + j) = *(const float4*)(src + col0 + cc + j);
            return;
        }
    }
    int Keff = (EPI == 3) ? 4*d : d;
    int nIters = Keff >> 5;

    extern __shared__ __align__(16) char dynsm[];
    uint32_t asb = (uint32_t)__cvta_generic_to_shared(dynsm);
    uint32_t bsb = asb + 4*ASTAGE;

    int wm = warp >> 2, wn = warp & 3;
    float c[4][4][4];
    #pragma unroll
    for (int i=0;i<4;i++)
        #pragma unroll
        for (int j=0;j<4;j++)
            #pragma unroll
            for (int r=0;r<4;r++) c[i][j][r]=0.f;

    int ar  = tid >> 1;
    int ach = (tid & 1) * 16;
    int rowA0 = byr*128 + ar;
    int rowA = (EPI == 0) ? g_perm[rowA0] : rowA0;
    const __half* Ag = A + (size_t)rowA*K + ach;
    int bk  = tid >> 3;
    int bn0 = (tid & 7) * 16;
    const __half* Bg = B + (size_t)bk*N + col0 + bn0;

    uint32_t aSlot = asb + ar*80 + ach*2;
    uint32_t bSlot = bsb + bk*272 + bn0*2;

    // prologue: up to 3 stages
    int inflight = 0;
    #pragma unroll
    for (int p = 0; p < 3; p++) {
        if (p < nIters) {
            const __half* Agp = Ag + p*32;
            const __half* Bgp = Bg + (size_t)(p*32)*N;
            cp_async16(aSlot + p*ASTAGE, Agp);
            cp_async16(aSlot + p*ASTAGE + 16, Agp + 8);
            cp_async16(bSlot + p*BSTAGE, Bgp);
            cp_async16(bSlot + p*BSTAGE + 16, Bgp + 8);
            cp_commit();
            inflight++;
        }
    }

    int st = 0;
    for (int it = 0; it < nIters; it++) {
        cp_waitg(inflight - 1);
        inflight--;
        __syncthreads();
        if (it + 3 < nIters) {
            int sn = st + 3; if (sn >= 4) sn -= 4;
            const __half* Agn = Ag + (it + 3)*32;
            const __half* Bgn = Bg + (size_t)((it + 3)*32)*N;
            cp_async16(aSlot + sn*ASTAGE, Agn);
            cp_async16(aSlot + sn*ASTAGE + 16, Agn + 8);
            cp_async16(bSlot + sn*BSTAGE, Bgn);
            cp_async16(bSlot + sn*BSTAGE + 16, Bgn + 8);
            cp_commit();
            inflight++;
        }
        uint32_t ab = asb + st*ASTAGE;
        uint32_t bb = bsb + st*BSTAGE;
        #pragma unroll
        for (int kk = 0; kk < 32; kk += 16) {
            uint32_t af[4][4];
            #pragma unroll
            for (int am = 0; am < 4; am++) {
                int m = lane >> 3;
                int row = wm*64 + am*16 + (lane & 7) + (m & 1)*8;
                int col = kk + (m >> 1)*8;
                ldsm_x4(af[am][0], af[am][1], af[am][2], af[am][3], ab + row*80 + col*2);
            }
            #pragma unroll
            for (int an = 0; an < 4; an++) {
                int brow = kk + (lane & 15);
                int bcol = wn*32 + an*8;
                uint32_t b0, b1;
                ldsm_x2t(b0, b1, bb + brow*272 + bcol*2);
                #pragma unroll
                for (int am = 0; am < 4; am++)
                    mma_f16(c[am][an], af[am], b0, b1);
            }
        }
        st++; if (st >= 4) st -= 4;
    }

    float aval = (EPI == 3) ? alpha[0] : 0.f;
    #pragma unroll
    for (int am = 0; am < 4; am++) {
        int r0 = byr*128 + wm*64 + am*16 + (lane>>2);
        int r1 = r0 + 8;
        float gate0 = (EPI == 3) ? (aval * g_rps[r0] + 1.f) : 0.f;
        float gate1 = (EPI == 3) ? (aval * g_rps[r1] + 1.f) : 0.f;
        int org0 = (EPI == 1 || EPI == 3) ? g_perm[r0] : 0;
        int org1 = (EPI == 1 || EPI == 3) ? g_perm[r1] : 0;
        #pragma unroll
        for (int an = 0; an < 4; an++) {
            int col = col0 + wn*32 + an*8 + (lane&3)*2;
            #pragma unroll
            for (int h2 = 0; h2 < 2; h2++) {
                int r = h2 ? r1 : r0;
                int org = h2 ? org1 : org0;
                float gate = h2 ? gate1 : gate0;
                float v0 = c[am][an][2*h2], v1 = c[am][an][2*h2+1];
                if (EPI == 0) {
                    float o0 = ((col & 511) < d)     ? v0 : 0.f;
                    float o1 = (((col+1) & 511) < d) ? v1 : 0.f;
                    *(uint32_t*)((__half*)Cv + (size_t)r*N + col) = packh2(o0, o1);
                } else if (EPI == 1) {
                    size_t xi = (size_t)org*N + col;
                    float o0 = add[xi]   + ((col   < d) ? (v0 + bias[col])   : 0.f);
                    float o1 = add[xi+1] + ((col+1 < d) ? (v1 + bias[col+1]) : 0.f);
                    *(float2*)((float*)Cv + (size_t)r*N + col) = make_float2(o0, o1);
                } else if (EPI == 2) {
                    float o0 = gelu_t(v0 + bias[col]);
                    float o1 = gelu_t(v1 + bias[col+1]);
                    *(uint32_t*)((__half*)Cv + (size_t)r*N + col) = packh2(o0, o1);
                } else {
                    size_t zi = (size_t)r*N + col;
                    float z0 = (col   < d) ? (v0 + bias[col])   : 0.f;
                    float z1 = (col+1 < d) ? (v1 + bias[col+1]) : 0.f;
                    float o0 = add[zi]   + gate * z0;
                    float o1 = add[zi+1] + gate * z1;
                    *(float2*)((float*)Cv + (size_t)org*N + col) = make_float2(o0, o1);
                }
            }
        }
    }
}

// ---------------- fp16 flash attention, intra-block split-K (2 groups) ----------------
#define QS_OFF 0
#define KS_OFF(g) (4608 + (g)*4608)
#define VS_OFF(g) (13824 + (g)*4608)

__global__ void attn_kernel()   // 256 threads = 2 warp-groups of 4 warps
{
    __shared__ __align__(16) __half sm[23040];

    int b = blockIdx.y;
    int qi = blockIdx.x;            // 0..79
    int h, qt;
    if (qi < 32)      { h = 0; qt = qi; }
    else if (qi < 48) { h = 1; qt = 16 + (qi - 32); }
    else if (qi < 56) { h = 2; qt = 24 + (qi - 48); }
    else if (qi < 64) { h = 3; qt = 24 + (qi - 56); }
    else              { h = 4 + ((qi - 64) >> 2); qt = 28 + ((qi - 64) & 3); }
    int kt0 = (h == 0) ? 0 : (h == 1) ? 16 : (h < 4) ? 24 : 28;
    int nz = kt0 * 64;

    int tid = threadIdx.x;
    int lane = tid & 31;
    int warp = tid >> 5;
    int grp = warp >> 2;            // 0/1
    int w4 = warp & 3;
    int ltid = tid & 127;

    int half = (32 - kt0) >> 1;
    int ktbeg = kt0 + grp*half;

    __half* Qs = sm + QS_OFF;
    __half* Ks = sm + KS_OFF(grp);
    __half* Vs = sm + VS_OFF(grp);
    uint32_t vsb = (uint32_t)__cvta_generic_to_shared(Vs);

    const __half* qb = g_qkv + (size_t)(b*NN + qt*64)*1536 + h*64;
    for (int i = tid; i < 512; i += 256) {
        int n = i >> 3, c8 = (i & 7) * 8;
        *(uint4*)(&Qs[n*72 + c8]) = *(const uint4*)(qb + (size_t)n*1536 + c8);
    }
    __syncthreads();

    uint32_t qf[4][4];
    {
        int r = w4*16 + (lane >> 2);
        #pragma unroll
        for (int ka = 0; ka < 4; ka++) {
            int cc = ka*16 + (lane & 3)*2;
            qf[ka][0] = *(const uint32_t*)(&Qs[r*72 + cc]);
            qf[ka][1] = *(const uint32_t*)(&Qs[(r+8)*72 + cc]);
            qf[ka][2] = *(const uint32_t*)(&Qs[r*72 + cc + 8]);
            qf[ka][3] = *(const uint32_t*)(&Qs[(r+8)*72 + cc + 8]);
        }
    }

    float o[8][4];
    #pragma unroll
    for (int i=0;i<8;i++)
        #pragma unroll
        for (int j=0;j<4;j++) o[i][j]=0.f;
    float m0, m1, l0, l1;
    if (grp == 0 && nz > 0) { m0 = 0.f; m1 = 0.f; l0 = (float)nz; l1 = (float)nz; }
    else                    { m0 = -1e30f; m1 = -1e30f; l0 = 0.f; l1 = 0.f; }

    for (int ii = 0; ii < half; ii++) {
        int kt = ktbeg + ii;
        __syncthreads();
        const __half* kb = g_qkv + (size_t)(b*NN + kt*64)*1536 + 512 + h*64;
        for (int i = ltid; i < 512; i += 128) {
            int n = i >> 3, c8 = (i & 7) * 8;
            *(uint4*)(&Ks[n*72 + c8]) = *(const uint4*)(kb + (size_t)n*1536 + c8);
            *(uint4*)(&Vs[n*72 + c8]) = *(const uint4*)(kb + 512 + (size_t)n*1536 + c8);
        }
        __syncthreads();

        float s[8][4];
        #pragma unroll
        for (int i=0;i<8;i++)
            #pragma unroll
            for (int j=0;j<4;j++) s[i][j]=0.f;
        #pragma unroll
        for (int ka = 0; ka < 4; ka++) {
            #pragma unroll
            for (int na = 0; na < 8; na++) {
                int n = na*8 + (lane >> 2);
                int k = ka*16 + (lane & 3)*2;
                uint32_t b0 = *(const uint32_t*)(&Ks[n*72 + k]);
                uint32_t b1 = *(const uint32_t*)(&Ks[n*72 + k + 8]);
                mma_f16(s[na], qf[ka], b0, b1);
            }
        }

        float mx0 = -1e30f, mx1 = -1e30f;
        #pragma unroll
        for (int na = 0; na < 8; na++) {
            s[na][0]*=0.125f; s[na][1]*=0.125f; s[na][2]*=0.125f; s[na][3]*=0.125f;
            mx0 = fmaxf(mx0, fmaxf(s[na][0], s[na][1]));
            mx1 = fmaxf(mx1, fmaxf(s[na][2], s[na][3]));
        }
        mx0 = fmaxf(mx0, __shfl_xor_sync(0xffffffffu, mx0, 1));
        mx0 = fmaxf(mx0, __shfl_xor_sync(0xffffffffu, mx0, 2));
        mx1 = fmaxf(mx1, __shfl_xor_sync(0xffffffffu, mx1, 1));
        mx1 = fmaxf(mx1, __shfl_xor_sync(0xffffffffu, mx1, 2));
        float mn0 = fmaxf(m0, mx0), mn1 = fmaxf(m1, mx1);
        float sc0 = __expf(m0 - mn0), sc1 = __expf(m1 - mn1);
        m0 = mn0; m1 = mn1;

        float sum0 = 0.f, sum1 = 0.f;
        #pragma unroll
        for (int na = 0; na < 8; na++) {
            s[na][0] = __expf(s[na][0] - m0);
            s[na][1] = __expf(s[na][1] - m0);
            s[na][2] = __expf(s[na][2] - m1);
            s[na][3] = __expf(s[na][3] - m1);
            sum0 += s[na][0] + s[na][1];
            sum1 += s[na][2] + s[na][3];
        }
        sum0 += __shfl_xor_sync(0xffffffffu, sum0, 1);
        sum0 += __shfl_xor_sync(0xffffffffu, sum0, 2);
        sum1 += __shfl_xor_sync(0xffffffffu, sum1, 1);
        sum1 += __shfl_xor_sync(0xffffffffu, sum1, 2);
        l0 = l0*sc0 + sum0;
        l1 = l1*sc1 + sum1;

        #pragma unroll
        for (int da = 0; da < 8; da++) {
            o[da][0]*=sc0; o[da][1]*=sc0; o[da][2]*=sc1; o[da][3]*=sc1;
        }

        #pragma unroll
        for (int ka = 0; ka < 4; ka++) {
            uint32_t pa[4];
            pa[0] = packh2(s[2*ka][0],   s[2*ka][1]);
            pa[1] = packh2(s[2*ka][2],   s[2*ka][3]);
            pa[2] = packh2(s[2*ka+1][0], s[2*ka+1][1]);
            pa[3] = packh2(s[2*ka+1][2], s[2*ka+1][3]);
            uint32_t rowaddr = vsb + (ka*16 + (lane & 15))*144;
            #pragma unroll
            for (int da = 0; da < 8; da++) {
                uint32_t b0, b1;
                ldsm_x2t(b0, b1, rowaddr + da*16);
                mma_f16(o[da], pa, b0, b1);
            }
        }
    }

    __syncthreads();
    float* so = (float*)sm;
    float* sml = so + 64*66;
    int r0 = w4*16 + (lane >> 2);
    int r1 = r0 + 8;
    if (grp == 1) {
        #pragma unroll
        for (int da = 0; da < 8; da++) {
            int col = da*8 + (lane&3)*2;
            *(float2*)(&so[r0*66 + col]) = make_float2(o[da][0], o[da][1]);
            *(float2*)(&so[r1*66 + col]) = make_float2(o[da][2], o[da][3]);
        }
        if ((lane & 3) == 0) {
            sml[r0] = m0; sml[64 + r0] = l0;
            sml[r1] = m1; sml[64 + r1] = l1;
        }
    }
    __syncthreads();
    if (grp == 0) {
        float m1s0 = sml[r0], l1s0 = sml[64 + r0];
        float m1s1 = sml[r1], l1s1 = sml[64 + r1];
        float M0 = fmaxf(m0, m1s0), M1 = fmaxf(m1, m1s1);
        float a0 = __expf(m0 - M0), b0s = __expf(m1s0 - M0);
        float a1 = __expf(m1 - M1), b1s = __expf(m1s1 - M1);
        float L0 = l0*a0 + l1s0*b0s;
        float L1 = l1*a1 + l1s1*b1s;
        float inv0 = 1.f / L0, inv1 = 1.f / L1;
        int tok0 = b*NN + qt*64 + r0;
        int tok1 = tok0 + 8;
        #pragma unroll
        for (int da = 0; da < 8; da++) {
            int col = da*8 + (lane&3)*2;
            float2 p0 = *(float2*)(&so[r0*66 + col]);
            float2 p1 = *(float2*)(&so[r1*66 + col]);
            float f00 = (o[da][0]*a0 + p0.x*b0s) * inv0;
            float f01 = (o[da][1]*a0 + p0.y*b0s) * inv0;
            float f10 = (o[da][2]*a1 + p1.x*b1s) * inv1;
            float f11 = (o[da][3]*a1 + p1.y*b1s) * inv1;
            int gcol = h*64 + col;
            *(uint32_t*)(g_o + (size_t)tok0*DD + gcol) = packh2(f00, f01);
            *(uint32_t*)(g_o + (size_t)tok1*DD + gcol) = packh2(f10, f11);
        }
    }
}

// ---------------- launcher ----------------
extern "C" void kernel_launch(void* const* d_in, const int* in_sizes, int n_in,
                              void* d_out, int out_size)
{
    const float* x     = (const float*)d_in[0];
    const float* r_w   = (const float*)d_in[1];
    const float* r_b   = (const float*)d_in[2];
    const float* g1    = (const float*)d_in[3];
    const float* b1    = (const float*)d_in[4];
    const float* g2    = (const float*)d_in[5];
    const float* b2    = (const float*)d_in[6];
    const float* w_qkv = (const float*)d_in[7];
    const float* w_o   = (const float*)d_in[8];
    const float* b_o   = (const float*)d_in[9];
    const float* w1    = (const float*)d_in[10];
    const float* b1f   = (const float*)d_in[11];
    const float* w2    = (const float*)d_in[12];
    const float* b2f   = (const float*)d_in[13];
    const float* alpha = (const float*)d_in[14];
    float* out = (float*)d_out;

    __half *p_h, *p_qkv, *p_o, *p_hid, *p_wh;
    float *p_z;
    cudaGetSymbolAddress((void**)&p_h,   g_h);
    cudaGetSymbolAddress((void**)&p_qkv, g_qkv);
    cudaGetSymbolAddress((void**)&p_o,   g_o);
    cudaGetSymbolAddress((void**)&p_z,   g_z);
    cudaGetSymbolAddress((void**)&p_hid, g_hid);
    cudaGetSymbolAddress((void**)&p_wh,  g_wh);

    cudaFuncSetAttribute(tgemm_kernel<0>, cudaFuncAttributeMaxDynamicSharedMemorySize, GEMM_SMEM);
    cudaFuncSetAttribute(tgemm_kernel<1>, cudaFuncAttributeMaxDynamicSharedMemorySize, GEMM_SMEM);
    cudaFuncSetAttribute(tgemm_kernel<2>, cudaFuncAttributeMaxDynamicSharedMemorySize, GEMM_SMEM);
    cudaFuncSetAttribute(tgemm_kernel<3>, cudaFuncAttributeMaxDynamicSharedMemorySize, GEMM_SMEM);

    // LN1 + router + weight conversion (fused)
    prep_kernel<<<TOK/8 + (W_TOTAL/4 + 255)/256, 256>>>(x, g1, b1, p_h, r_w, r_b,
                                                        w_qkv, w_o, w1, w2);
    sort_kernel<<<BB*EE, 1024>>>();
    claim_kernel<<<BB, 512>>>(out, out_size);

    // attention path
    tgemm_kernel<0><<<dim3(1536/128, TOK/128), 256, GEMM_SMEM>>>(p_h, p_wh + W_QKV_OFF, p_qkv, 1536, 512,
                                                                 nullptr, nullptr, nullptr);
    attn_kernel<<<dim3(80, BB), 256>>>();
    tgemm_kernel<1><<<dim3(512/128, TOK/128), 256, GEMM_SMEM>>>(p_o, p_wh + W_O_OFF, p_z, 512, 512,
                                                                b_o, x, nullptr);

    // feed-forward path
    ln_kernel<<<TOK/8, 256>>>(p_z, g2, b2, p_h);
    tgemm_kernel<2><<<dim3(2048/128, TOK/128), 256, GEMM_SMEM>>>(p_h, p_wh + W1_OFF, p_hid, 2048, 512,
                                                                 b1f, nullptr, nullptr);
    tgemm_kernel<3><<<dim3(512/128, TOK/128), 256, GEMM_SMEM>>>(p_hid, p_wh + W2_OFF, out, 512, 2048,
                                                                b2f, p_z, alpha);
}